// round 1
// baseline (speedup 1.0000x reference)
#include <cuda_runtime.h>
#include <cuda_fp16.h>
#include <cstdint>

// Problem dims (fixed by the dataset)
#define BB 8
#define SS 1024
#define DD 1024
#define HH 16
#define HD 64
#define MTOT (BB * SS)  // 8192

// ---------------------------------------------------------------------------
// Scratch (allocation-free rule: __device__ globals)
// ---------------------------------------------------------------------------
__device__ __half g_enc[MTOT * DD];       // encoding_output fp16
__device__ __half g_query[MTOT * DD];     // input_query fp16
__device__ __half g_Wqk[DD * 2 * DD];
__device__ __half g_Wv[DD * DD];
__device__ __half g_Wo[DD * DD];
__device__ __half g_Q[MTOT * DD];         // [B,H,S,hd]
__device__ __half g_K[MTOT * DD];         // [B,H,S,hd]
__device__ __half g_V[MTOT * DD];         // [B,H,S,hd]
__device__ __half g_ctx[MTOT * DD];       // [B*S, H*hd] (ready as A for out-proj)

// ---------------------------------------------------------------------------
// fp32 -> fp16 conversion (vectorized, grid-stride)
// which: 0=enc 1=query 2=Wqk 3=Wv 4=Wo
// ---------------------------------------------------------------------------
__global__ void convert_kernel(const float* __restrict__ src, int which, int n4) {
    __half* dst;
    switch (which) {
        case 0: dst = g_enc; break;
        case 1: dst = g_query; break;
        case 2: dst = g_Wqk; break;
        case 3: dst = g_Wv; break;
        default: dst = g_Wo; break;
    }
    int i = blockIdx.x * blockDim.x + threadIdx.x;
    int stride = gridDim.x * blockDim.x;
    __half2* d2 = (__half2*)dst;
    for (; i < n4; i += stride) {
        float4 v = ((const float4*)src)[i];
        d2[2 * i]     = __floats2half2_rn(v.x, v.y);
        d2[2 * i + 1] = __floats2half2_rn(v.z, v.w);
    }
}

// ---------------------------------------------------------------------------
// mma.sync m16n8k16 fp16 -> fp32
// ---------------------------------------------------------------------------
__device__ __forceinline__ void mma16816(float* c,
                                         uint32_t a0, uint32_t a1, uint32_t a2, uint32_t a3,
                                         uint32_t b0, uint32_t b1) {
    asm volatile(
        "mma.sync.aligned.m16n8k16.row.col.f32.f16.f16.f32 "
        "{%0,%1,%2,%3}, {%4,%5,%6,%7}, {%8,%9}, {%0,%1,%2,%3};\n"
        : "+f"(c[0]), "+f"(c[1]), "+f"(c[2]), "+f"(c[3])
        : "r"(a0), "r"(a1), "r"(a2), "r"(a3), "r"(b0), "r"(b1));
}

// ---------------------------------------------------------------------------
// Generic GEMM: C = A @ B (+bias), fp16 in, fp32 accum.
// BM=128, BN=128, BK=32, 256 threads = 8 warps (4 m x 2 n), warp tile 32x64.
// mode 0: A=g_enc   B=g_Wqk (N=2048) -> split into g_Q / g_K ([B,H,S,hd] fp16)
// mode 1: A=g_query B=g_Wv  (N=1024) -> g_V ([B,H,S,hd] fp16)
// mode 2: A=g_ctx   B=g_Wo  (N=1024) -> outF fp32 [M, 1024]
// ---------------------------------------------------------------------------
__global__ __launch_bounds__(256, 2)
void gemm_kernel(const float* __restrict__ bias, float* __restrict__ outF, int mode) {
    __shared__ __half As[128][40];   // pad 8: 80B rows -> conflict-free frags
    __shared__ __half Bst[128][40];  // B stored transposed: [n][k]

    const __half* A;
    const __half* Bm;
    int lda, ldb;
    if (mode == 0)      { A = g_enc;   Bm = g_Wqk; lda = 1024; ldb = 2048; }
    else if (mode == 1) { A = g_query; Bm = g_Wv;  lda = 1024; ldb = 1024; }
    else                { A = g_ctx;   Bm = g_Wo;  lda = 1024; ldb = 1024; }
    const int K = 1024;

    const int tid = threadIdx.x;
    const int lane = tid & 31, warp = tid >> 5;
    const int g = lane >> 2, tig = lane & 3;
    const int wm = warp & 3, wn = warp >> 2;
    const int bx = blockIdx.x, by = blockIdx.y;

    float acc[2][8][4];
#pragma unroll
    for (int mt = 0; mt < 2; mt++)
#pragma unroll
        for (int nt = 0; nt < 8; nt++)
#pragma unroll
            for (int q = 0; q < 4; q++) acc[mt][nt][q] = 0.f;

    const __half* Ab = A + (size_t)by * 128 * lda;
    const __half* Bb = Bm + bx * 128;

    uint4 aR[2], bR[2];

    // prologue: load tile k0=0
#pragma unroll
    for (int i = 0; i < 2; i++) {
        int s = tid + 256 * i;
        int r = s >> 2, kg = s & 3;
        aR[i] = *(const uint4*)(Ab + (size_t)r * lda + kg * 8);
        int kr = s >> 4, ng = s & 15;
        bR[i] = *(const uint4*)(Bb + (size_t)kr * ldb + ng * 8);
    }
#pragma unroll
    for (int i = 0; i < 2; i++) {
        int s = tid + 256 * i;
        int r = s >> 2, kg = s & 3;
        *(uint4*)&As[r][kg * 8] = aR[i];
        int kr = s >> 4, ng = s & 15;
        const __half* hv = (const __half*)&bR[i];
#pragma unroll
        for (int j = 0; j < 8; j++) Bst[ng * 8 + j][kr] = hv[j];
    }
    __syncthreads();

    for (int k0 = 0; k0 < K; k0 += 32) {
        const bool have_next = (k0 + 32 < K);
        if (have_next) {
#pragma unroll
            for (int i = 0; i < 2; i++) {
                int s = tid + 256 * i;
                int r = s >> 2, kg = s & 3;
                aR[i] = *(const uint4*)(Ab + (size_t)r * lda + (k0 + 32) + kg * 8);
                int kr = s >> 4, ng = s & 15;
                bR[i] = *(const uint4*)(Bb + (size_t)(k0 + 32 + kr) * ldb + ng * 8);
            }
        }
        // compute on current smem tile
#pragma unroll
        for (int kk = 0; kk < 32; kk += 16) {
            uint32_t af[2][4];
#pragma unroll
            for (int mt = 0; mt < 2; mt++) {
                int r = wm * 32 + mt * 16 + g;
                af[mt][0] = *(const uint32_t*)&As[r][kk + 2 * tig];
                af[mt][1] = *(const uint32_t*)&As[r + 8][kk + 2 * tig];
                af[mt][2] = *(const uint32_t*)&As[r][kk + 2 * tig + 8];
                af[mt][3] = *(const uint32_t*)&As[r + 8][kk + 2 * tig + 8];
            }
#pragma unroll
            for (int nt = 0; nt < 8; nt++) {
                int c = wn * 64 + nt * 8 + g;
                uint32_t b0 = *(const uint32_t*)&Bst[c][kk + 2 * tig];
                uint32_t b1 = *(const uint32_t*)&Bst[c][kk + 2 * tig + 8];
                mma16816(acc[0][nt], af[0][0], af[0][1], af[0][2], af[0][3], b0, b1);
                mma16816(acc[1][nt], af[1][0], af[1][1], af[1][2], af[1][3], b0, b1);
            }
        }
        __syncthreads();
        if (have_next) {
#pragma unroll
            for (int i = 0; i < 2; i++) {
                int s = tid + 256 * i;
                int r = s >> 2, kg = s & 3;
                *(uint4*)&As[r][kg * 8] = aR[i];
                int kr = s >> 4, ng = s & 15;
                const __half* hv = (const __half*)&bR[i];
#pragma unroll
                for (int j = 0; j < 8; j++) Bst[ng * 8 + j][kr] = hv[j];
            }
            __syncthreads();
        }
    }

    // epilogue
#pragma unroll
    for (int mt = 0; mt < 2; mt++) {
#pragma unroll
        for (int nt = 0; nt < 8; nt++) {
            int col = bx * 128 + wn * 64 + nt * 8 + 2 * tig;
            float bi0 = bias[col], bi1 = bias[col + 1];
#pragma unroll
            for (int hi = 0; hi < 2; hi++) {
                int row = by * 128 + wm * 32 + mt * 16 + g + hi * 8;
                float v0 = acc[mt][nt][hi * 2 + 0] + bi0;
                float v1 = acc[mt][nt][hi * 2 + 1] + bi1;
                if (mode == 2) {
                    *(float2*)(outF + (size_t)row * 1024 + col) = make_float2(v0, v1);
                } else if (mode == 1) {
                    int b = row >> 10, s = row & 1023;
                    int h = col >> 6, d = col & 63;
                    size_t idx = ((((size_t)b * HH + h) * SS + s) << 6) + d;
                    *(__half2*)(g_V + idx) = __floats2half2_rn(v0, v1);
                } else {
                    int b = row >> 10, s = row & 1023;
                    int h = col >> 7, w = col & 127;
                    int d = w & 63;
                    size_t idx = ((((size_t)b * HH + h) * SS + s) << 6) + d;
                    if (w < 64) *(__half2*)(g_Q + idx) = __floats2half2_rn(v0, v1);
                    else        *(__half2*)(g_K + idx) = __floats2half2_rn(v0, v1);
                }
            }
        }
    }
}

// ---------------------------------------------------------------------------
// Flash attention: grid (S/128, B*H), 256 threads (8 warps x 16 q-rows).
// Q tile 128x64 (pre-scaled by 1/8), KV tiles 64x64, online softmax,
// P fragments reused straight from the S accumulator layout.
// ---------------------------------------------------------------------------
__global__ __launch_bounds__(256, 1)
void flash_kernel() {
    __shared__ __half Qs[128][72];   // 144B rows: 16B-aligned, conflict-free frags
    __shared__ __half Ks[64][72];
    __shared__ __half Vst[64][72];   // V transposed: [hd][kv]

    const int tid = threadIdx.x;
    const int lane = tid & 31, warp = tid >> 5;
    const int g = lane >> 2, tig = lane & 3;
    const int bh = blockIdx.y;
    const int q0 = blockIdx.x * 128;
    const size_t base = (size_t)bh * SS * HD;

    // stage Q (scaled by 1/sqrt(hd) = 0.125, exact in fp16)
    const __half2 sc2 = __floats2half2_rn(0.125f, 0.125f);
#pragma unroll
    for (int i = 0; i < 4; i++) {
        int s = tid + 256 * i;
        int r = s >> 3, cg = s & 7;
        uint4 v = *(const uint4*)(g_Q + base + (size_t)(q0 + r) * HD + cg * 8);
        __half2* hv = (__half2*)&v;
        hv[0] = __hmul2(hv[0], sc2);
        hv[1] = __hmul2(hv[1], sc2);
        hv[2] = __hmul2(hv[2], sc2);
        hv[3] = __hmul2(hv[3], sc2);
        *(uint4*)&Qs[r][cg * 8] = v;
    }

    float o[8][4];
#pragma unroll
    for (int j = 0; j < 8; j++)
#pragma unroll
        for (int q = 0; q < 4; q++) o[j][q] = 0.f;
    float m0 = -1e30f, m1 = -1e30f, l0 = 0.f, l1 = 0.f;
    const float L2E = 1.44269504f;

    for (int kv0 = 0; kv0 < SS; kv0 += 64) {
        __syncthreads();
        // stage K (direct) and V (transposed)
#pragma unroll
        for (int i = 0; i < 2; i++) {
            int s = tid + 256 * i;
            int r = s >> 3, cg = s & 7;
            *(uint4*)&Ks[r][cg * 8] =
                *(const uint4*)(g_K + base + (size_t)(kv0 + r) * HD + cg * 8);
            uint4 v = *(const uint4*)(g_V + base + (size_t)(kv0 + r) * HD + cg * 8);
            const __half* hv = (const __half*)&v;
#pragma unroll
            for (int j = 0; j < 8; j++) Vst[cg * 8 + j][r] = hv[j];
        }
        __syncthreads();

        // S = Q @ K^T (scale already in Q)
        float sf[8][4];
#pragma unroll
        for (int nt = 0; nt < 8; nt++)
#pragma unroll
            for (int q = 0; q < 4; q++) sf[nt][q] = 0.f;
#pragma unroll
        for (int kk = 0; kk < 64; kk += 16) {
            int r = warp * 16 + g;
            uint32_t a0 = *(const uint32_t*)&Qs[r][kk + 2 * tig];
            uint32_t a1 = *(const uint32_t*)&Qs[r + 8][kk + 2 * tig];
            uint32_t a2 = *(const uint32_t*)&Qs[r][kk + 2 * tig + 8];
            uint32_t a3 = *(const uint32_t*)&Qs[r + 8][kk + 2 * tig + 8];
#pragma unroll
            for (int nt = 0; nt < 8; nt++) {
                uint32_t b0 = *(const uint32_t*)&Ks[nt * 8 + g][kk + 2 * tig];
                uint32_t b1 = *(const uint32_t*)&Ks[nt * 8 + g][kk + 2 * tig + 8];
                mma16816(sf[nt], a0, a1, a2, a3, b0, b1);
            }
        }

        // online softmax (rows g and g+8; cols spread over tig lanes)
        float mx0 = -1e30f, mx1 = -1e30f;
#pragma unroll
        for (int nt = 0; nt < 8; nt++) {
            mx0 = fmaxf(mx0, fmaxf(sf[nt][0], sf[nt][1]));
            mx1 = fmaxf(mx1, fmaxf(sf[nt][2], sf[nt][3]));
        }
        mx0 = fmaxf(mx0, __shfl_xor_sync(0xffffffffu, mx0, 1));
        mx0 = fmaxf(mx0, __shfl_xor_sync(0xffffffffu, mx0, 2));
        mx1 = fmaxf(mx1, __shfl_xor_sync(0xffffffffu, mx1, 1));
        mx1 = fmaxf(mx1, __shfl_xor_sync(0xffffffffu, mx1, 2));
        float mn0 = fmaxf(m0, mx0), mn1 = fmaxf(m1, mx1);
        float al0 = exp2f((m0 - mn0) * L2E);
        float al1 = exp2f((m1 - mn1) * L2E);
        float rs0 = 0.f, rs1 = 0.f;
#pragma unroll
        for (int nt = 0; nt < 8; nt++) {
            sf[nt][0] = exp2f((sf[nt][0] - mn0) * L2E);
            sf[nt][1] = exp2f((sf[nt][1] - mn0) * L2E);
            sf[nt][2] = exp2f((sf[nt][2] - mn1) * L2E);
            sf[nt][3] = exp2f((sf[nt][3] - mn1) * L2E);
            rs0 += sf[nt][0] + sf[nt][1];
            rs1 += sf[nt][2] + sf[nt][3];
        }
        rs0 += __shfl_xor_sync(0xffffffffu, rs0, 1);
        rs0 += __shfl_xor_sync(0xffffffffu, rs0, 2);
        rs1 += __shfl_xor_sync(0xffffffffu, rs1, 1);
        rs1 += __shfl_xor_sync(0xffffffffu, rs1, 2);
        l0 = l0 * al0 + rs0;
        l1 = l1 * al1 + rs1;
        m0 = mn0;
        m1 = mn1;
#pragma unroll
        for (int j = 0; j < 8; j++) {
            o[j][0] *= al0; o[j][1] *= al0;
            o[j][2] *= al1; o[j][3] *= al1;
        }

        // O += P @ V (P fragments straight from sf accumulator layout)
#pragma unroll
        for (int kt = 0; kt < 4; kt++) {
            __half2 pa0 = __floats2half2_rn(sf[2 * kt][0], sf[2 * kt][1]);
            __half2 pa1 = __floats2half2_rn(sf[2 * kt][2], sf[2 * kt][3]);
            __half2 pa2 = __floats2half2_rn(sf[2 * kt + 1][0], sf[2 * kt + 1][1]);
            __half2 pa3 = __floats2half2_rn(sf[2 * kt + 1][2], sf[2 * kt + 1][3]);
            uint32_t a0 = *(uint32_t*)&pa0;
            uint32_t a1 = *(uint32_t*)&pa1;
            uint32_t a2 = *(uint32_t*)&pa2;
            uint32_t a3 = *(uint32_t*)&pa3;
#pragma unroll
            for (int j = 0; j < 8; j++) {
                uint32_t b0 = *(const uint32_t*)&Vst[j * 8 + g][kt * 16 + 2 * tig];
                uint32_t b1 = *(const uint32_t*)&Vst[j * 8 + g][kt * 16 + 2 * tig + 8];
                mma16816(o[j], a0, a1, a2, a3, b0, b1);
            }
        }
    }

    // write ctx[b*S + q, h*64 + d] fp16
    float il0 = 1.f / l0, il1 = 1.f / l1;
    int b = bh >> 4, h = bh & 15;
    int r0 = q0 + warp * 16 + g;
    size_t o0 = ((size_t)(b * SS + r0)) * DD + h * HD + 2 * tig;
    size_t o1 = o0 + (size_t)8 * DD;
#pragma unroll
    for (int j = 0; j < 8; j++) {
        *(__half2*)(g_ctx + o0 + j * 8) = __floats2half2_rn(o[j][0] * il0, o[j][1] * il0);
        *(__half2*)(g_ctx + o1 + j * 8) = __floats2half2_rn(o[j][2] * il1, o[j][3] * il1);
    }
}

// ---------------------------------------------------------------------------
// Launch: graph-capturable, default stream ordering carries dependencies.
// Input order (setup_inputs): input_query, encoding_output, Wqk, bqk, Wv, bv, Wo, bo
// ---------------------------------------------------------------------------
extern "C" void kernel_launch(void* const* d_in, const int* in_sizes, int n_in,
                              void* d_out, int out_size) {
    (void)in_sizes; (void)n_in; (void)out_size;
    const float* input_query = (const float*)d_in[0];
    const float* encoding    = (const float*)d_in[1];
    const float* bqk         = (const float*)d_in[3];
    const float* bv          = (const float*)d_in[5];
    const float* bo          = (const float*)d_in[7];
    const float* Wqk         = (const float*)d_in[2];
    const float* Wv          = (const float*)d_in[4];
    const float* Wo          = (const float*)d_in[6];
    float* out = (float*)d_out;

    convert_kernel<<<512, 256>>>(encoding,    0, MTOT * DD / 4);
    convert_kernel<<<512, 256>>>(input_query, 1, MTOT * DD / 4);
    convert_kernel<<<128, 256>>>(Wqk,         2, DD * 2 * DD / 4);
    convert_kernel<<<64,  256>>>(Wv,          3, DD * DD / 4);
    convert_kernel<<<64,  256>>>(Wo,          4, DD * DD / 4);

    gemm_kernel<<<dim3(16, 64), 256>>>(bqk, nullptr, 0);  // QK projection -> g_Q, g_K
    gemm_kernel<<<dim3(8, 64),  256>>>(bv,  nullptr, 1);  // V projection  -> g_V
    flash_kernel<<<dim3(8, 128), 256>>>();                // attention     -> g_ctx
    gemm_kernel<<<dim3(8, 64),  256>>>(bo,  out,     2);  // out projection -> d_out
}

// round 5
// speedup vs baseline: 2.0943x; 2.0943x over previous
#include <cuda_runtime.h>
#include <cuda_fp16.h>
#include <cstdint>

// Problem dims (fixed by the dataset)
#define BB 8
#define SS 1024
#define DD 1024
#define HH 16
#define HD 64
#define MTOT (BB * SS)  // 8192

// ---------------------------------------------------------------------------
// Scratch (allocation-free rule: __device__ globals)
// ---------------------------------------------------------------------------
__device__ __align__(16) __half g_enc[MTOT * DD];       // encoding_output fp16
__device__ __align__(16) __half g_query[MTOT * DD];     // input_query fp16
__device__ __align__(16) __half g_WqkT[2 * DD * DD];    // Wqk^T  [2048][1024] K-major
__device__ __align__(16) __half g_WvT[DD * DD];         // Wv^T   [1024][1024]
__device__ __align__(16) __half g_WoT[DD * DD];         // Wo^T   [1024][1024]
__device__ __align__(16) __half g_Q[MTOT * DD];         // [B,H,S,hd]
__device__ __align__(16) __half g_K[MTOT * DD];         // [B,H,S,hd]
__device__ __align__(16) __half g_V[MTOT * DD];         // [B,H,S,hd]
__device__ __align__(16) __half g_ctx[MTOT * DD];       // [B*S, H*hd]

// ---------------------------------------------------------------------------
// cp.async helpers (baseline PTX, works under compute_103)
// ---------------------------------------------------------------------------
__device__ __forceinline__ uint32_t smem_u32(const void* p) {
    uint32_t a;
    asm("{ .reg .u64 t; cvta.to.shared.u64 t, %1; cvt.u32.u64 %0, t; }" : "=r"(a) : "l"(p));
    return a;
}
#define CP_ASYNC16(dst, src) \
    asm volatile("cp.async.cg.shared.global [%0], [%1], 16;" :: "r"(dst), "l"(src))
#define CP_COMMIT() asm volatile("cp.async.commit_group;")
#define CP_WAIT0() asm volatile("cp.async.wait_group 0;" ::: "memory")
#define CP_WAIT1() asm volatile("cp.async.wait_group 1;" ::: "memory")

// ---------------------------------------------------------------------------
// mma.sync m16n8k16 fp16 -> fp32
// ---------------------------------------------------------------------------
__device__ __forceinline__ void mma16816(float* c,
                                         uint32_t a0, uint32_t a1, uint32_t a2, uint32_t a3,
                                         uint32_t b0, uint32_t b1) {
    asm volatile(
        "mma.sync.aligned.m16n8k16.row.col.f32.f16.f16.f32 "
        "{%0,%1,%2,%3}, {%4,%5,%6,%7}, {%8,%9}, {%0,%1,%2,%3};\n"
        : "+f"(c[0]), "+f"(c[1]), "+f"(c[2]), "+f"(c[3])
        : "r"(a0), "r"(a1), "r"(a2), "r"(a3), "r"(b0), "r"(b1));
}

__device__ __forceinline__ uint32_t pack_h2(float a, float b) {
    __half2 h = __floats2half2_rn(a, b);
    return *(uint32_t*)&h;
}

// ---------------------------------------------------------------------------
// fp32 -> fp16 conversion of activations (which: 0=enc 1=query)
// ---------------------------------------------------------------------------
__global__ void convert_kernel(const float* __restrict__ src, int which, int n4) {
    __half* dst = which == 0 ? g_enc : g_query;
    int i = blockIdx.x * blockDim.x + threadIdx.x;
    int stride = gridDim.x * blockDim.x;
    __half2* d2 = (__half2*)dst;
    for (; i < n4; i += stride) {
        float4 v = ((const float4*)src)[i];
        d2[2 * i]     = __floats2half2_rn(v.x, v.y);
        d2[2 * i + 1] = __floats2half2_rn(v.z, v.w);
    }
}

// ---------------------------------------------------------------------------
// Weight transpose + convert: W [K=1024][N] fp32 -> Wt [N][1024] fp16
// which: 0=Wqk(N=2048) 1=Wv 2=Wo
// ---------------------------------------------------------------------------
__global__ void transpose_w(const float* __restrict__ src, int which) {
    __shared__ float t[32][33];
    const int N = (which == 0) ? 2048 : 1024;
    __half* dst = (which == 0) ? g_WqkT : (which == 1) ? g_WvT : g_WoT;
    const int nb = blockIdx.x * 32, kb = blockIdx.y * 32;
    const int tx = threadIdx.x, ty = threadIdx.y;  // 32 x 8
#pragma unroll
    for (int j = 0; j < 32; j += 8)
        t[ty + j][tx] = src[(size_t)(kb + ty + j) * N + nb + tx];
    __syncthreads();
#pragma unroll
    for (int j = 0; j < 32; j += 8)
        dst[(size_t)(nb + ty + j) * 1024 + kb + tx] = __float2half(t[tx][ty + j]);
}

// ---------------------------------------------------------------------------
// HMMA GEMM: C[M,N] = A[M,1024] @ Bt[N,1024]^T (+bias)
// CTA tile 128x128, BK=64, cp.async double-buffered (1 group in flight),
// 8 warps (4m x 2n), warp tile 32x64. Padded rows: 72 halves = 144B.
// mode 0: A=g_enc   Bt=g_WqkT -> split g_Q/g_K fp16 [B,H,S,hd]
// mode 1: A=g_query Bt=g_WvT  -> g_V fp16
// mode 2: A=g_ctx   Bt=g_WoT  -> fp32 out [M,1024]
// ---------------------------------------------------------------------------
#define TILE_H (128 * 72)                     // halves per tile (A or B)
#define GSMEM_BYTES (4 * TILE_H * 2)          // 2 buffers x (A+B) = 73728 B

__global__ __launch_bounds__(256)
void gemm_hmma(const float* __restrict__ bias, float* __restrict__ outF, int mode) {
    extern __shared__ __half sm[];
    const int tid = threadIdx.x;
    const int lane = tid & 31, warp = tid >> 5;
    const int g = lane >> 2, tig = lane & 3;
    const int wm = warp & 3, wn = warp >> 2;
    const int bx = blockIdx.x, by = blockIdx.y;

    const __half* A;
    const __half* Bt;
    if (mode == 0)      { A = g_enc;   Bt = g_WqkT; }
    else if (mode == 1) { A = g_query; Bt = g_WvT;  }
    else                { A = g_ctx;   Bt = g_WoT;  }

    const __half* Ab = A + (size_t)by * 128 * 1024;
    const __half* Bb = Bt + (size_t)bx * 128 * 1024;

    // smem bases (halves): buf b: A at b*2*TILE_H, B at b*2*TILE_H + TILE_H
    const uint32_t smb = smem_u32(sm);

    // per-thread load slots: s = tid + 256*i -> row = s>>3, 16B chunk c = s&7
    int rowi[4], coli[4];
    uint32_t off16[4];
#pragma unroll
    for (int i = 0; i < 4; i++) {
        int s = tid + 256 * i;
        rowi[i] = s >> 3;
        coli[i] = (s & 7) * 8;                 // halves
        off16[i] = rowi[i] * 144 + (s & 7) * 16;  // bytes within tile
    }

    float acc[2][8][4];
#pragma unroll
    for (int mt = 0; mt < 2; mt++)
#pragma unroll
        for (int nt = 0; nt < 8; nt++)
#pragma unroll
            for (int q = 0; q < 4; q++) acc[mt][nt][q] = 0.f;

    // prologue: load tile 0 into buf 0
    {
        const uint32_t sA = smb, sB = smb + TILE_H * 2;
#pragma unroll
        for (int i = 0; i < 4; i++) {
            CP_ASYNC16(sA + off16[i], Ab + (size_t)rowi[i] * 1024 + coli[i]);
            CP_ASYNC16(sB + off16[i], Bb + (size_t)rowi[i] * 1024 + coli[i]);
        }
        CP_COMMIT();
    }

    for (int kt = 0; kt < 16; kt++) {
        const int buf = kt & 1;
        if (kt + 1 < 16) {
            const int nbuf = buf ^ 1;
            const uint32_t sA = smb + nbuf * 2 * TILE_H * 2;
            const uint32_t sB = sA + TILE_H * 2;
            const int k0 = (kt + 1) * 64;
#pragma unroll
            for (int i = 0; i < 4; i++) {
                CP_ASYNC16(sA + off16[i], Ab + (size_t)rowi[i] * 1024 + k0 + coli[i]);
                CP_ASYNC16(sB + off16[i], Bb + (size_t)rowi[i] * 1024 + k0 + coli[i]);
            }
            CP_COMMIT();
            CP_WAIT1();   // tile kt complete; prefetch kt+1 still in flight
        } else {
            CP_WAIT0();
        }
        __syncthreads();

        const __half* As = sm + buf * 2 * TILE_H;          // [128][72]
        const __half* Bs = As + TILE_H;                    // [128][72]
#pragma unroll
        for (int kk = 0; kk < 64; kk += 16) {
            uint32_t af[2][4];
#pragma unroll
            for (int mt = 0; mt < 2; mt++) {
                int r = wm * 32 + mt * 16 + g;
                af[mt][0] = *(const uint32_t*)(As + r * 72 + kk + 2 * tig);
                af[mt][1] = *(const uint32_t*)(As + (r + 8) * 72 + kk + 2 * tig);
                af[mt][2] = *(const uint32_t*)(As + r * 72 + kk + 2 * tig + 8);
                af[mt][3] = *(const uint32_t*)(As + (r + 8) * 72 + kk + 2 * tig + 8);
            }
#pragma unroll
            for (int nt = 0; nt < 8; nt++) {
                int c = wn * 64 + nt * 8 + g;
                uint32_t b0 = *(const uint32_t*)(Bs + c * 72 + kk + 2 * tig);
                uint32_t b1 = *(const uint32_t*)(Bs + c * 72 + kk + 2 * tig + 8);
                mma16816(acc[0][nt], af[0][0], af[0][1], af[0][2], af[0][3], b0, b1);
                mma16816(acc[1][nt], af[1][0], af[1][1], af[1][2], af[1][3], b0, b1);
            }
        }
        __syncthreads();
    }

    // epilogue (same layout as proven R0 kernel)
#pragma unroll
    for (int mt = 0; mt < 2; mt++) {
#pragma unroll
        for (int nt = 0; nt < 8; nt++) {
            int col = bx * 128 + wn * 64 + nt * 8 + 2 * tig;
            float bi0 = bias[col], bi1 = bias[col + 1];
#pragma unroll
            for (int hi = 0; hi < 2; hi++) {
                int row = by * 128 + wm * 32 + mt * 16 + g + hi * 8;
                float v0 = acc[mt][nt][hi * 2 + 0] + bi0;
                float v1 = acc[mt][nt][hi * 2 + 1] + bi1;
                if (mode == 2) {
                    *(float2*)(outF + (size_t)row * 1024 + col) = make_float2(v0, v1);
                } else if (mode == 1) {
                    int b = row >> 10, s = row & 1023;
                    int h = col >> 6, d = col & 63;
                    size_t idx = ((((size_t)b * HH + h) * SS + s) << 6) + d;
                    *(__half2*)(g_V + idx) = __floats2half2_rn(v0, v1);
                } else {
                    int b = row >> 10, s = row & 1023;
                    int h = col >> 7, w = col & 127;
                    int d = w & 63;
                    size_t idx = ((((size_t)b * HH + h) * SS + s) << 6) + d;
                    if (w < 64) *(__half2*)(g_Q + idx) = __floats2half2_rn(v0, v1);
                    else        *(__half2*)(g_K + idx) = __floats2half2_rn(v0, v1);
                }
            }
        }
    }
}

// ---------------------------------------------------------------------------
// Flash attention: grid (S/128, B*H), 256 threads (8 warps x 16 q-rows).
// Q tile 128x64 (pre-scaled by 1/8), KV tiles 64x64, online softmax.
// ---------------------------------------------------------------------------
__global__ __launch_bounds__(256, 2)
void flash_kernel() {
    __shared__ __half Qs[128][72];
    __shared__ __half Ks[64][72];
    __shared__ __half Vst[64][72];   // V transposed: [hd][kv]

    const int tid = threadIdx.x;
    const int lane = tid & 31, warp = tid >> 5;
    const int g = lane >> 2, tig = lane & 3;
    const int bh = blockIdx.y;
    const int q0 = blockIdx.x * 128;
    const size_t base = (size_t)bh * SS * HD;

    const __half2 sc2 = __floats2half2_rn(0.125f, 0.125f);
#pragma unroll
    for (int i = 0; i < 4; i++) {
        int s = tid + 256 * i;
        int r = s >> 3, cg = s & 7;
        uint4 v = *(const uint4*)(g_Q + base + (size_t)(q0 + r) * HD + cg * 8);
        __half2* hv = (__half2*)&v;
        hv[0] = __hmul2(hv[0], sc2);
        hv[1] = __hmul2(hv[1], sc2);
        hv[2] = __hmul2(hv[2], sc2);
        hv[3] = __hmul2(hv[3], sc2);
        *(uint4*)&Qs[r][cg * 8] = v;
    }

    float o[8][4];
#pragma unroll
    for (int j = 0; j < 8; j++)
#pragma unroll
        for (int q = 0; q < 4; q++) o[j][q] = 0.f;
    float m0 = -1e30f, m1 = -1e30f, l0 = 0.f, l1 = 0.f;
    const float L2E = 1.44269504f;

    for (int kv0 = 0; kv0 < SS; kv0 += 64) {
        __syncthreads();
#pragma unroll
        for (int i = 0; i < 2; i++) {
            int s = tid + 256 * i;
            int r = s >> 3, cg = s & 7;
            *(uint4*)&Ks[r][cg * 8] =
                *(const uint4*)(g_K + base + (size_t)(kv0 + r) * HD + cg * 8);
            uint4 v = *(const uint4*)(g_V + base + (size_t)(kv0 + r) * HD + cg * 8);
            const __half* hv = (const __half*)&v;
#pragma unroll
            for (int j = 0; j < 8; j++) Vst[cg * 8 + j][r] = hv[j];
        }
        __syncthreads();

        float sf[8][4];
#pragma unroll
        for (int nt = 0; nt < 8; nt++)
#pragma unroll
            for (int q = 0; q < 4; q++) sf[nt][q] = 0.f;
#pragma unroll
        for (int kk = 0; kk < 64; kk += 16) {
            int r = warp * 16 + g;
            uint32_t a0 = *(const uint32_t*)&Qs[r][kk + 2 * tig];
            uint32_t a1 = *(const uint32_t*)&Qs[r + 8][kk + 2 * tig];
            uint32_t a2 = *(const uint32_t*)&Qs[r][kk + 2 * tig + 8];
            uint32_t a3 = *(const uint32_t*)&Qs[r + 8][kk + 2 * tig + 8];
#pragma unroll
            for (int nt = 0; nt < 8; nt++) {
                uint32_t b0 = *(const uint32_t*)&Ks[nt * 8 + g][kk + 2 * tig];
                uint32_t b1 = *(const uint32_t*)&Ks[nt * 8 + g][kk + 2 * tig + 8];
                mma16816(sf[nt], a0, a1, a2, a3, b0, b1);
            }
        }

        float mx0 = -1e30f, mx1 = -1e30f;
#pragma unroll
        for (int nt = 0; nt < 8; nt++) {
            mx0 = fmaxf(mx0, fmaxf(sf[nt][0], sf[nt][1]));
            mx1 = fmaxf(mx1, fmaxf(sf[nt][2], sf[nt][3]));
        }
        mx0 = fmaxf(mx0, __shfl_xor_sync(0xffffffffu, mx0, 1));
        mx0 = fmaxf(mx0, __shfl_xor_sync(0xffffffffu, mx0, 2));
        mx1 = fmaxf(mx1, __shfl_xor_sync(0xffffffffu, mx1, 1));
        mx1 = fmaxf(mx1, __shfl_xor_sync(0xffffffffu, mx1, 2));
        float mn0 = fmaxf(m0, mx0), mn1 = fmaxf(m1, mx1);
        float al0 = exp2f((m0 - mn0) * L2E);
        float al1 = exp2f((m1 - mn1) * L2E);
        float rs0 = 0.f, rs1 = 0.f;
#pragma unroll
        for (int nt = 0; nt < 8; nt++) {
            sf[nt][0] = exp2f((sf[nt][0] - mn0) * L2E);
            sf[nt][1] = exp2f((sf[nt][1] - mn0) * L2E);
            sf[nt][2] = exp2f((sf[nt][2] - mn1) * L2E);
            sf[nt][3] = exp2f((sf[nt][3] - mn1) * L2E);
            rs0 += sf[nt][0] + sf[nt][1];
            rs1 += sf[nt][2] + sf[nt][3];
        }
        rs0 += __shfl_xor_sync(0xffffffffu, rs0, 1);
        rs0 += __shfl_xor_sync(0xffffffffu, rs0, 2);
        rs1 += __shfl_xor_sync(0xffffffffu, rs1, 1);
        rs1 += __shfl_xor_sync(0xffffffffu, rs1, 2);
        l0 = l0 * al0 + rs0;
        l1 = l1 * al1 + rs1;
        m0 = mn0;
        m1 = mn1;
#pragma unroll
        for (int j = 0; j < 8; j++) {
            o[j][0] *= al0; o[j][1] *= al0;
            o[j][2] *= al1; o[j][3] *= al1;
        }

#pragma unroll
        for (int kt = 0; kt < 4; kt++) {
            __half2 pa0 = __floats2half2_rn(sf[2 * kt][0], sf[2 * kt][1]);
            __half2 pa1 = __floats2half2_rn(sf[2 * kt][2], sf[2 * kt][3]);
            __half2 pa2 = __floats2half2_rn(sf[2 * kt + 1][0], sf[2 * kt + 1][1]);
            __half2 pa3 = __floats2half2_rn(sf[2 * kt + 1][2], sf[2 * kt + 1][3]);
            uint32_t a0 = *(uint32_t*)&pa0;
            uint32_t a1 = *(uint32_t*)&pa1;
            uint32_t a2 = *(uint32_t*)&pa2;
            uint32_t a3 = *(uint32_t*)&pa3;
#pragma unroll
            for (int j = 0; j < 8; j++) {
                uint32_t b0 = *(const uint32_t*)&Vst[j * 8 + g][kt * 16 + 2 * tig];
                uint32_t b1 = *(const uint32_t*)&Vst[j * 8 + g][kt * 16 + 2 * tig + 8];
                mma16816(o[j], a0, a1, a2, a3, b0, b1);
            }
        }
    }

    float il0 = 1.f / l0, il1 = 1.f / l1;
    int b = bh >> 4, h = bh & 15;
    int r0 = q0 + warp * 16 + g;
    size_t o0 = ((size_t)(b * SS + r0)) * DD + h * HD + 2 * tig;
    size_t o1 = o0 + (size_t)8 * DD;
#pragma unroll
    for (int j = 0; j < 8; j++) {
        *(__half2*)(g_ctx + o0 + j * 8) = __floats2half2_rn(o[j][0] * il0, o[j][1] * il0);
        *(__half2*)(g_ctx + o1 + j * 8) = __floats2half2_rn(o[j][2] * il1, o[j][3] * il1);
    }
}

// ---------------------------------------------------------------------------
// Launch (graph-capturable; default-stream ordering carries dependencies).
// Input order: input_query, encoding_output, Wqk, bqk, Wv, bv, Wo, bo
// ---------------------------------------------------------------------------
extern "C" void kernel_launch(void* const* d_in, const int* in_sizes, int n_in,
                              void* d_out, int out_size) {
    (void)in_sizes; (void)n_in; (void)out_size;
    const float* input_query = (const float*)d_in[0];
    const float* encoding    = (const float*)d_in[1];
    const float* Wqk         = (const float*)d_in[2];
    const float* bqk         = (const float*)d_in[3];
    const float* Wv          = (const float*)d_in[4];
    const float* bv          = (const float*)d_in[5];
    const float* Wo          = (const float*)d_in[6];
    const float* bo          = (const float*)d_in[7];
    float* out = (float*)d_out;

    cudaFuncSetAttribute(gemm_hmma, cudaFuncAttributeMaxDynamicSharedMemorySize, GSMEM_BYTES);

    convert_kernel<<<512, 256>>>(encoding,    0, MTOT * DD / 4);
    convert_kernel<<<512, 256>>>(input_query, 1, MTOT * DD / 4);
    transpose_w<<<dim3(64, 32), dim3(32, 8)>>>(Wqk, 0);
    transpose_w<<<dim3(32, 32), dim3(32, 8)>>>(Wv, 1);
    transpose_w<<<dim3(32, 32), dim3(32, 8)>>>(Wo, 2);

    gemm_hmma<<<dim3(16, 64), 256, GSMEM_BYTES>>>(bqk, nullptr, 0);  // QK proj
    gemm_hmma<<<dim3(8, 64),  256, GSMEM_BYTES>>>(bv,  nullptr, 1);  // V proj
    flash_kernel<<<dim3(8, 128), 256>>>();                           // attention
    gemm_hmma<<<dim3(8, 64),  256, GSMEM_BYTES>>>(bo,  out,     2);  // out proj
}

// round 7
// speedup vs baseline: 2.6269x; 1.2543x over previous
#include <cuda_runtime.h>
#include <cuda_fp16.h>
#include <cstdint>

// Problem dims (fixed by the dataset)
#define BB 8
#define SS 1024
#define DD 1024
#define HH 16
#define HD 64
#define MTOT (BB * SS)  // 8192

// ---------------------------------------------------------------------------
// Scratch (allocation-free rule: __device__ globals)
// ---------------------------------------------------------------------------
__device__ __align__(16) __half g_enc[MTOT * DD];
__device__ __align__(16) __half g_query[MTOT * DD];
__device__ __align__(16) __half g_WqkT[2 * DD * DD];    // Wqk^T [2048][1024] K-major
__device__ __align__(16) __half g_WvT[DD * DD];
__device__ __align__(16) __half g_WoT[DD * DD];
__device__ __align__(16) __half g_Q[MTOT * DD];         // [B,H,S,hd]
__device__ __align__(16) __half g_K[MTOT * DD];         // [B,H,S,hd]
__device__ __align__(16) __half g_V[MTOT * DD];         // [B,H,S,hd]
__device__ __align__(16) __half g_ctx[MTOT * DD];       // [B*S, H*hd]

// ---------------------------------------------------------------------------
// PTX helpers (all baseline PTX — safe under compute_103 virtual arch)
// ---------------------------------------------------------------------------
__device__ __forceinline__ uint32_t smem_u32(const void* p) {
    uint32_t a;
    asm("{ .reg .u64 t; cvta.to.shared.u64 t, %1; cvt.u32.u64 %0, t; }" : "=r"(a) : "l"(p));
    return a;
}
#define CP_ASYNC16(dst, src) \
    asm volatile("cp.async.cg.shared.global [%0], [%1], 16;" :: "r"(dst), "l"(src))
#define CP_COMMIT() asm volatile("cp.async.commit_group;")
#define CP_WAIT0() asm volatile("cp.async.wait_group 0;" ::: "memory")
#define CP_WAIT1() asm volatile("cp.async.wait_group 1;" ::: "memory")

#define LDSM_X4(r0, r1, r2, r3, addr)                                         \
    asm volatile("ldmatrix.sync.aligned.m8n8.x4.shared.b16 {%0,%1,%2,%3}, [%4];" \
                 : "=r"(r0), "=r"(r1), "=r"(r2), "=r"(r3) : "r"(addr))
#define LDSM_X4_T(r0, r1, r2, r3, addr)                                       \
    asm volatile("ldmatrix.sync.aligned.m8n8.x4.trans.shared.b16 {%0,%1,%2,%3}, [%4];" \
                 : "=r"(r0), "=r"(r1), "=r"(r2), "=r"(r3) : "r"(addr))

__device__ __forceinline__ void mma16816(float* c,
                                         uint32_t a0, uint32_t a1, uint32_t a2, uint32_t a3,
                                         uint32_t b0, uint32_t b1) {
    asm volatile(
        "mma.sync.aligned.m16n8k16.row.col.f32.f16.f16.f32 "
        "{%0,%1,%2,%3}, {%4,%5,%6,%7}, {%8,%9}, {%0,%1,%2,%3};\n"
        : "+f"(c[0]), "+f"(c[1]), "+f"(c[2]), "+f"(c[3])
        : "r"(a0), "r"(a1), "r"(a2), "r"(a3), "r"(b0), "r"(b1));
}

__device__ __forceinline__ uint32_t pack_h2(float a, float b) {
    __half2 h = __floats2half2_rn(a, b);
    return *(uint32_t*)&h;
}

// Lane-dependent ldmatrix address offsets (bytes), 144B row pitch.
// A / V-trans:   row = (l&7)+(l&8), col(+8 halves) when l>=16
// B non-trans:   row = (l&7)+((l&16)>>1), col(+8 halves) when l&8
__device__ __forceinline__ uint32_t ldsm_a_off(int l) {
    return (uint32_t)(((l & 7) + (l & 8)) * 144 + ((l & 16) >> 1) * 2);
}
__device__ __forceinline__ uint32_t ldsm_b_off(int l) {
    return (uint32_t)(((l & 7) + ((l & 16) >> 1)) * 144 + (l & 8) * 2);
}

// ---------------------------------------------------------------------------
// fp32 -> fp16 conversion of activations (which: 0=enc 1=query)
// ---------------------------------------------------------------------------
__global__ void convert_kernel(const float* __restrict__ src, int which, int n4) {
    __half* dst = which == 0 ? g_enc : g_query;
    int i = blockIdx.x * blockDim.x + threadIdx.x;
    int stride = gridDim.x * blockDim.x;
    __half2* d2 = (__half2*)dst;
    for (; i < n4; i += stride) {
        float4 v = ((const float4*)src)[i];
        d2[2 * i]     = __floats2half2_rn(v.x, v.y);
        d2[2 * i + 1] = __floats2half2_rn(v.z, v.w);
    }
}

// ---------------------------------------------------------------------------
// Weight transpose + convert: W [K=1024][N] fp32 -> Wt [N][1024] fp16
// ---------------------------------------------------------------------------
__global__ void transpose_w(const float* __restrict__ src, int which) {
    __shared__ float t[32][33];
    const int N = (which == 0) ? 2048 : 1024;
    __half* dst = (which == 0) ? g_WqkT : (which == 1) ? g_WvT : g_WoT;
    const int nb = blockIdx.x * 32, kb = blockIdx.y * 32;
    const int tx = threadIdx.x, ty = threadIdx.y;  // 32 x 8
#pragma unroll
    for (int j = 0; j < 32; j += 8)
        t[ty + j][tx] = src[(size_t)(kb + ty + j) * N + nb + tx];
    __syncthreads();
#pragma unroll
    for (int j = 0; j < 32; j += 8)
        dst[(size_t)(nb + ty + j) * 1024 + kb + tx] = __float2half(t[tx][ty + j]);
}

// ---------------------------------------------------------------------------
// HMMA GEMM: C[M,N] = A[M,1024] @ Bt[N,1024]^T (+bias)
// CTA tile 128x128, BK=64, 3-stage cp.async ring (1 sync/iter), ldmatrix frags.
// ---------------------------------------------------------------------------
#define TILE_H (128 * 72)                      // halves per tile
#define GSMEM_BYTES (3 * 2 * TILE_H * 2)       // 3 stages x (A+B) = 110592 B

__global__ __launch_bounds__(256)
void gemm_hmma(const float* __restrict__ bias, float* __restrict__ outF, int mode) {
    extern __shared__ __half sm[];
    const int tid = threadIdx.x;
    const int lane = tid & 31, warp = tid >> 5;
    const int g = lane >> 2, tig = lane & 3;
    const int wm = warp & 3, wn = warp >> 2;
    const int bx = blockIdx.x, by = blockIdx.y;

    const __half* A;
    const __half* Bt;
    if (mode == 0)      { A = g_enc;   Bt = g_WqkT; }
    else if (mode == 1) { A = g_query; Bt = g_WvT;  }
    else                { A = g_ctx;   Bt = g_WoT;  }

    const __half* Ab = A + (size_t)by * 128 * 1024;
    const __half* Bb = Bt + (size_t)bx * 128 * 1024;
    const uint32_t smb = smem_u32(sm);

    // per-thread load slots: s = tid + 256*i -> row = s>>3, 16B chunk = s&7
    int rowi[4], coli[4];
    uint32_t off16[4];
#pragma unroll
    for (int i = 0; i < 4; i++) {
        int s = tid + 256 * i;
        rowi[i] = s >> 3;
        coli[i] = (s & 7) * 8;
        off16[i] = rowi[i] * 144 + (s & 7) * 16;
    }
    const uint32_t aoff = ldsm_a_off(lane);
    const uint32_t boff = ldsm_b_off(lane);

    float acc[2][8][4];
#pragma unroll
    for (int mt = 0; mt < 2; mt++)
#pragma unroll
        for (int nt = 0; nt < 8; nt++)
#pragma unroll
            for (int q = 0; q < 4; q++) acc[mt][nt][q] = 0.f;

    // prologue: issue tiles 0, 1
#pragma unroll
    for (int p = 0; p < 2; p++) {
        const uint32_t sA = smb + p * 2 * TILE_H * 2;
        const uint32_t sB = sA + TILE_H * 2;
        const int k0 = p * 64;
#pragma unroll
        for (int i = 0; i < 4; i++) {
            CP_ASYNC16(sA + off16[i], Ab + (size_t)rowi[i] * 1024 + k0 + coli[i]);
            CP_ASYNC16(sB + off16[i], Bb + (size_t)rowi[i] * 1024 + k0 + coli[i]);
        }
        CP_COMMIT();
    }

    for (int kt = 0; kt < 16; kt++) {
        if (kt + 1 < 16) CP_WAIT1(); else CP_WAIT0();
        __syncthreads();
        if (kt + 2 < 16) {
            const int st = (kt + 2) % 3;
            const uint32_t sA = smb + st * 2 * TILE_H * 2;
            const uint32_t sB = sA + TILE_H * 2;
            const int k0 = (kt + 2) * 64;
#pragma unroll
            for (int i = 0; i < 4; i++) {
                CP_ASYNC16(sA + off16[i], Ab + (size_t)rowi[i] * 1024 + k0 + coli[i]);
                CP_ASYNC16(sB + off16[i], Bb + (size_t)rowi[i] * 1024 + k0 + coli[i]);
            }
            CP_COMMIT();
        }
        const int st = kt % 3;
        const uint32_t sA = smb + st * 2 * TILE_H * 2;
        const uint32_t sB = sA + TILE_H * 2;
#pragma unroll
        for (int kk = 0; kk < 64; kk += 16) {
            uint32_t af[2][4];
#pragma unroll
            for (int mt = 0; mt < 2; mt++)
                LDSM_X4(af[mt][0], af[mt][1], af[mt][2], af[mt][3],
                        sA + (wm * 32 + mt * 16) * 144 + kk * 2 + aoff);
#pragma unroll
            for (int ntp = 0; ntp < 4; ntp++) {
                uint32_t b0a, b1a, b0b, b1b;
                LDSM_X4(b0a, b1a, b0b, b1b,
                        sB + (wn * 64 + ntp * 16) * 144 + kk * 2 + boff);
                mma16816(acc[0][2 * ntp],     af[0][0], af[0][1], af[0][2], af[0][3], b0a, b1a);
                mma16816(acc[0][2 * ntp + 1], af[0][0], af[0][1], af[0][2], af[0][3], b0b, b1b);
                mma16816(acc[1][2 * ntp],     af[1][0], af[1][1], af[1][2], af[1][3], b0a, b1a);
                mma16816(acc[1][2 * ntp + 1], af[1][0], af[1][1], af[1][2], af[1][3], b0b, b1b);
            }
        }
    }

    // epilogue (proven layout)
#pragma unroll
    for (int mt = 0; mt < 2; mt++) {
#pragma unroll
        for (int nt = 0; nt < 8; nt++) {
            int col = bx * 128 + wn * 64 + nt * 8 + 2 * tig;
            float bi0 = bias[col], bi1 = bias[col + 1];
#pragma unroll
            for (int hi = 0; hi < 2; hi++) {
                int row = by * 128 + wm * 32 + mt * 16 + g + hi * 8;
                float v0 = acc[mt][nt][hi * 2 + 0] + bi0;
                float v1 = acc[mt][nt][hi * 2 + 1] + bi1;
                if (mode == 2) {
                    *(float2*)(outF + (size_t)row * 1024 + col) = make_float2(v0, v1);
                } else if (mode == 1) {
                    int b = row >> 10, s = row & 1023;
                    int h = col >> 6, d = col & 63;
                    size_t idx = ((((size_t)b * HH + h) * SS + s) << 6) + d;
                    *(__half2*)(g_V + idx) = __floats2half2_rn(v0, v1);
                } else {
                    int b = row >> 10, s = row & 1023;
                    int h = col >> 7, w = col & 127;
                    int d = w & 63;
                    size_t idx = ((((size_t)b * HH + h) * SS + s) << 6) + d;
                    if (w < 64) *(__half2*)(g_Q + idx) = __floats2half2_rn(v0, v1);
                    else        *(__half2*)(g_K + idx) = __floats2half2_rn(v0, v1);
                }
            }
        }
    }
}

// ---------------------------------------------------------------------------
// Flash attention: grid (S/128, B*H), 256 threads (8 warps x 16 q-rows).
// cp.async double-buffered K/V (natural layout), ldmatrix fragments
// (V via .trans — no scalar transpose), online softmax.
// smem (halves): Q[128*72] | K0[64*72] | K1 | V0 | V1  = 55296 B dynamic.
// ---------------------------------------------------------------------------
#define T64 (64 * 72)
#define FSMEM_BYTES ((128 * 72 + 4 * T64) * 2)

__global__ __launch_bounds__(256, 2)
void flash_kernel() {
    extern __shared__ __half fsm[];
    __half* Qs = fsm;                    // [128][72]
    const uint32_t smb = smem_u32(fsm);
    const uint32_t qb = smb;
    const uint32_t kb0 = smb + 128 * 72 * 2;
    const uint32_t vb0 = kb0 + 2 * T64 * 2;

    const int tid = threadIdx.x;
    const int lane = tid & 31, warp = tid >> 5;
    const int g = lane >> 2, tig = lane & 3;
    const int bh = blockIdx.y;
    const int q0 = blockIdx.x * 128;
    const size_t base = (size_t)bh * SS * HD;

    const uint32_t aoff = ldsm_a_off(lane);
    const uint32_t boff = ldsm_b_off(lane);

    // K/V tile load slots: s = tid + 256*i (i<2): row = s>>3 (0..63), chunk = s&7
    int krow[2], kcol[2];
    uint32_t koff[2];
#pragma unroll
    for (int i = 0; i < 2; i++) {
        int s = tid + 256 * i;
        krow[i] = s >> 3;
        kcol[i] = (s & 7) * 8;
        koff[i] = krow[i] * 144 + (s & 7) * 16;
    }

    // stage Q (scaled by 1/8, exact in fp16)
    const __half2 sc2 = __floats2half2_rn(0.125f, 0.125f);
#pragma unroll
    for (int i = 0; i < 4; i++) {
        int s = tid + 256 * i;
        int r = s >> 3, cg = s & 7;
        uint4 v = *(const uint4*)(g_Q + base + (size_t)(q0 + r) * HD + cg * 8);
        __half2* hv = (__half2*)&v;
        hv[0] = __hmul2(hv[0], sc2);
        hv[1] = __hmul2(hv[1], sc2);
        hv[2] = __hmul2(hv[2], sc2);
        hv[3] = __hmul2(hv[3], sc2);
        *(uint4*)&Qs[r * 72 + cg * 8] = v;
    }

    // issue tile 0
#pragma unroll
    for (int i = 0; i < 2; i++) {
        CP_ASYNC16(kb0 + koff[i], g_K + base + (size_t)krow[i] * HD + kcol[i]);
        CP_ASYNC16(vb0 + koff[i], g_V + base + (size_t)krow[i] * HD + kcol[i]);
    }
    CP_COMMIT();

    float o[8][4];
#pragma unroll
    for (int j = 0; j < 8; j++)
#pragma unroll
        for (int q = 0; q < 4; q++) o[j][q] = 0.f;
    float m0 = -1e30f, m1 = -1e30f, l0 = 0.f, l1 = 0.f;
    const float L2E = 1.44269504f;

    for (int it = 0; it < 16; it++) {
        const int buf = it & 1;
        __syncthreads();   // Q ready (it=0); prior readers of buf^1 done (it>0)
        if (it + 1 < 16) {
            const int nb = buf ^ 1;
            const size_t src = base + (size_t)(it + 1) * 64 * HD;
#pragma unroll
            for (int i = 0; i < 2; i++) {
                CP_ASYNC16(kb0 + nb * T64 * 2 + koff[i], g_K + src + (size_t)krow[i] * HD + kcol[i]);
                CP_ASYNC16(vb0 + nb * T64 * 2 + koff[i], g_V + src + (size_t)krow[i] * HD + kcol[i]);
            }
            CP_COMMIT();
            CP_WAIT1();
        } else {
            CP_WAIT0();
        }
        __syncthreads();   // tile 'it' visible to all warps

        const uint32_t Kb = kb0 + buf * T64 * 2;
        const uint32_t Vb = vb0 + buf * T64 * 2;

        // S = Q @ K^T (scale folded into Q)
        float sf[8][4];
#pragma unroll
        for (int nt = 0; nt < 8; nt++)
#pragma unroll
            for (int q = 0; q < 4; q++) sf[nt][q] = 0.f;
#pragma unroll
        for (int kk = 0; kk < 64; kk += 16) {
            uint32_t a0, a1, a2, a3;
            LDSM_X4(a0, a1, a2, a3, qb + (warp * 16) * 144 + kk * 2 + aoff);
#pragma unroll
            for (int ntp = 0; ntp < 4; ntp++) {
                uint32_t b0a, b1a, b0b, b1b;
                LDSM_X4(b0a, b1a, b0b, b1b, Kb + (ntp * 16) * 144 + kk * 2 + boff);
                mma16816(sf[2 * ntp],     a0, a1, a2, a3, b0a, b1a);
                mma16816(sf[2 * ntp + 1], a0, a1, a2, a3, b0b, b1b);
            }
        }

        // online softmax (rows g, g+8; cols spread over tig lanes)
        float mx0 = -1e30f, mx1 = -1e30f;
#pragma unroll
        for (int nt = 0; nt < 8; nt++) {
            mx0 = fmaxf(mx0, fmaxf(sf[nt][0], sf[nt][1]));
            mx1 = fmaxf(mx1, fmaxf(sf[nt][2], sf[nt][3]));
        }
        mx0 = fmaxf(mx0, __shfl_xor_sync(0xffffffffu, mx0, 1));
        mx0 = fmaxf(mx0, __shfl_xor_sync(0xffffffffu, mx0, 2));
        mx1 = fmaxf(mx1, __shfl_xor_sync(0xffffffffu, mx1, 1));
        mx1 = fmaxf(mx1, __shfl_xor_sync(0xffffffffu, mx1, 2));
        float mn0 = fmaxf(m0, mx0), mn1 = fmaxf(m1, mx1);
        float al0 = exp2f((m0 - mn0) * L2E);
        float al1 = exp2f((m1 - mn1) * L2E);
        float rs0 = 0.f, rs1 = 0.f;
#pragma unroll
        for (int nt = 0; nt < 8; nt++) {
            sf[nt][0] = exp2f((sf[nt][0] - mn0) * L2E);
            sf[nt][1] = exp2f((sf[nt][1] - mn0) * L2E);
            sf[nt][2] = exp2f((sf[nt][2] - mn1) * L2E);
            sf[nt][3] = exp2f((sf[nt][3] - mn1) * L2E);
            rs0 += sf[nt][0] + sf[nt][1];
            rs1 += sf[nt][2] + sf[nt][3];
        }
        rs0 += __shfl_xor_sync(0xffffffffu, rs0, 1);
        rs0 += __shfl_xor_sync(0xffffffffu, rs0, 2);
        rs1 += __shfl_xor_sync(0xffffffffu, rs1, 1);
        rs1 += __shfl_xor_sync(0xffffffffu, rs1, 2);
        l0 = l0 * al0 + rs0;
        l1 = l1 * al1 + rs1;
        m0 = mn0;
        m1 = mn1;
#pragma unroll
        for (int j = 0; j < 8; j++) {
            o[j][0] *= al0; o[j][1] *= al0;
            o[j][2] *= al1; o[j][3] *= al1;
        }

        // O += P @ V  (V fragments via ldmatrix.trans from natural [kv][hd])
#pragma unroll
        for (int kt = 0; kt < 4; kt++) {
            uint32_t a0 = pack_h2(sf[2 * kt][0], sf[2 * kt][1]);
            uint32_t a1 = pack_h2(sf[2 * kt][2], sf[2 * kt][3]);
            uint32_t a2 = pack_h2(sf[2 * kt + 1][0], sf[2 * kt + 1][1]);
            uint32_t a3 = pack_h2(sf[2 * kt + 1][2], sf[2 * kt + 1][3]);
#pragma unroll
            for (int jp = 0; jp < 4; jp++) {
                uint32_t v0, v1, v2, v3;
                LDSM_X4_T(v0, v1, v2, v3, Vb + (kt * 16) * 144 + (jp * 16) * 2 + aoff);
                mma16816(o[2 * jp],     a0, a1, a2, a3, v0, v1);
                mma16816(o[2 * jp + 1], a0, a1, a2, a3, v2, v3);
            }
        }
    }

    // write ctx[b*S + q, h*64 + d] fp16
    float il0 = 1.f / l0, il1 = 1.f / l1;
    int b = bh >> 4, h = bh & 15;
    int r0 = q0 + warp * 16 + g;
    size_t o0 = ((size_t)(b * SS + r0)) * DD + h * HD + 2 * tig;
    size_t o1 = o0 + (size_t)8 * DD;
#pragma unroll
    for (int j = 0; j < 8; j++) {
        *(__half2*)(g_ctx + o0 + j * 8) = __floats2half2_rn(o[j][0] * il0, o[j][1] * il0);
        *(__half2*)(g_ctx + o1 + j * 8) = __floats2half2_rn(o[j][2] * il1, o[j][3] * il1);
    }
}

// ---------------------------------------------------------------------------
// Launch (graph-capturable; default-stream ordering carries dependencies).
// Input order: input_query, encoding_output, Wqk, bqk, Wv, bv, Wo, bo
// ---------------------------------------------------------------------------
extern "C" void kernel_launch(void* const* d_in, const int* in_sizes, int n_in,
                              void* d_out, int out_size) {
    (void)in_sizes; (void)n_in; (void)out_size;
    const float* input_query = (const float*)d_in[0];
    const float* encoding    = (const float*)d_in[1];
    const float* Wqk         = (const float*)d_in[2];
    const float* bqk         = (const float*)d_in[3];
    const float* Wv          = (const float*)d_in[4];
    const float* bv          = (const float*)d_in[5];
    const float* Wo          = (const float*)d_in[6];
    const float* bo          = (const float*)d_in[7];
    float* out = (float*)d_out;

    cudaFuncSetAttribute(gemm_hmma, cudaFuncAttributeMaxDynamicSharedMemorySize, GSMEM_BYTES);
    cudaFuncSetAttribute(flash_kernel, cudaFuncAttributeMaxDynamicSharedMemorySize, FSMEM_BYTES);

    convert_kernel<<<512, 256>>>(encoding,    0, MTOT * DD / 4);
    convert_kernel<<<512, 256>>>(input_query, 1, MTOT * DD / 4);
    transpose_w<<<dim3(64, 32), dim3(32, 8)>>>(Wqk, 0);
    transpose_w<<<dim3(32, 32), dim3(32, 8)>>>(Wv, 1);
    transpose_w<<<dim3(32, 32), dim3(32, 8)>>>(Wo, 2);

    gemm_hmma<<<dim3(16, 64), 256, GSMEM_BYTES>>>(bqk, nullptr, 0);  // QK proj
    gemm_hmma<<<dim3(8, 64),  256, GSMEM_BYTES>>>(bv,  nullptr, 1);  // V proj
    flash_kernel<<<dim3(8, 128), 256, FSMEM_BYTES>>>();              // attention
    gemm_hmma<<<dim3(8, 64),  256, GSMEM_BYTES>>>(bo,  out,     2);  // out proj
}

// round 8
// speedup vs baseline: 2.7154x; 1.0337x over previous
#include <cuda_runtime.h>
#include <cuda_fp16.h>
#include <cstdint>

// Problem dims (fixed by the dataset)
#define BB 8
#define SS 1024
#define DD 1024
#define HH 16
#define HD 64
#define MTOT (BB * SS)  // 8192

// ---------------------------------------------------------------------------
// Scratch (allocation-free rule: __device__ globals)
// ---------------------------------------------------------------------------
__device__ __align__(16) __half g_enc[MTOT * DD];
__device__ __align__(16) __half g_query[MTOT * DD];
__device__ __align__(16) __half g_WqkT[2 * DD * DD];    // Wqk^T [2048][1024] K-major
__device__ __align__(16) __half g_WvT[DD * DD];
__device__ __align__(16) __half g_WoT[DD * DD];
__device__ __align__(16) __half g_Q[MTOT * DD];         // [B,H,S,hd]
__device__ __align__(16) __half g_K[MTOT * DD];         // [B,H,S,hd]
__device__ __align__(16) __half g_V[MTOT * DD];         // [B,H,S,hd]
__device__ __align__(16) __half g_ctx[MTOT * DD];       // [B*S, H*hd]

// ---------------------------------------------------------------------------
// PTX helpers (baseline PTX — safe under compute_103 virtual arch)
// ---------------------------------------------------------------------------
__device__ __forceinline__ uint32_t smem_u32(const void* p) {
    uint32_t a;
    asm("{ .reg .u64 t; cvta.to.shared.u64 t, %1; cvt.u32.u64 %0, t; }" : "=r"(a) : "l"(p));
    return a;
}
#define CP_ASYNC16(dst, src) \
    asm volatile("cp.async.cg.shared.global [%0], [%1], 16;" :: "r"(dst), "l"(src))
#define CP_COMMIT() asm volatile("cp.async.commit_group;")
#define CP_WAIT0() asm volatile("cp.async.wait_group 0;" ::: "memory")
#define CP_WAIT1() asm volatile("cp.async.wait_group 1;" ::: "memory")

#define LDSM_X4(r0, r1, r2, r3, addr)                                         \
    asm volatile("ldmatrix.sync.aligned.m8n8.x4.shared.b16 {%0,%1,%2,%3}, [%4];" \
                 : "=r"(r0), "=r"(r1), "=r"(r2), "=r"(r3) : "r"(addr))
#define LDSM_X4_T(r0, r1, r2, r3, addr)                                       \
    asm volatile("ldmatrix.sync.aligned.m8n8.x4.trans.shared.b16 {%0,%1,%2,%3}, [%4];" \
                 : "=r"(r0), "=r"(r1), "=r"(r2), "=r"(r3) : "r"(addr))

__device__ __forceinline__ void mma16816(float* c,
                                         uint32_t a0, uint32_t a1, uint32_t a2, uint32_t a3,
                                         uint32_t b0, uint32_t b1) {
    asm volatile(
        "mma.sync.aligned.m16n8k16.row.col.f32.f16.f16.f32 "
        "{%0,%1,%2,%3}, {%4,%5,%6,%7}, {%8,%9}, {%0,%1,%2,%3};\n"
        : "+f"(c[0]), "+f"(c[1]), "+f"(c[2]), "+f"(c[3])
        : "r"(a0), "r"(a1), "r"(a2), "r"(a3), "r"(b0), "r"(b1));
}

__device__ __forceinline__ uint32_t pack_h2(float a, float b) {
    __half2 h = __floats2half2_rn(a, b);
    return *(uint32_t*)&h;
}

// Lane-dependent ldmatrix address offsets (bytes), 144B row pitch.
__device__ __forceinline__ uint32_t ldsm_a_off(int l) {
    return (uint32_t)(((l & 7) + (l & 8)) * 144 + ((l & 16) >> 1) * 2);
}
__device__ __forceinline__ uint32_t ldsm_b_off(int l) {
    return (uint32_t)(((l & 7) + ((l & 16) >> 1)) * 144 + (l & 8) * 2);
}

// ---------------------------------------------------------------------------
// Activations fp32 -> fp16 (blockIdx.z: 0=enc, 1=query)
// ---------------------------------------------------------------------------
__global__ void convert_kernel(const float* __restrict__ enc, const float* __restrict__ qry) {
    const float* src = blockIdx.z == 0 ? enc : qry;
    __half* dst = blockIdx.z == 0 ? g_enc : g_query;
    int i = blockIdx.x * blockDim.x + threadIdx.x;
    int stride = gridDim.x * blockDim.x;
    __half2* d2 = (__half2*)dst;
    const int n4 = MTOT * DD / 4;
    for (; i < n4; i += stride) {
        float4 v = ((const float4*)src)[i];
        d2[2 * i]     = __floats2half2_rn(v.x, v.y);
        d2[2 * i + 1] = __floats2half2_rn(v.z, v.w);
    }
}

// ---------------------------------------------------------------------------
// Weight transpose + convert, all three in one launch (blockIdx.z selects).
// W [K=1024][N] fp32 -> Wt [N][1024] fp16
// ---------------------------------------------------------------------------
__global__ void transpose_w(const float* __restrict__ Wqk, const float* __restrict__ Wv,
                            const float* __restrict__ Wo) {
    __shared__ float t[32][33];
    const int z = blockIdx.z;
    if (z > 0 && blockIdx.x >= 32) return;
    const float* src = (z == 0) ? Wqk : (z == 1) ? Wv : Wo;
    __half* dst = (z == 0) ? g_WqkT : (z == 1) ? g_WvT : g_WoT;
    const int N = (z == 0) ? 2048 : 1024;
    const int nb = blockIdx.x * 32, kb = blockIdx.y * 32;
    const int tx = threadIdx.x, ty = threadIdx.y;  // 32 x 8
#pragma unroll
    for (int j = 0; j < 32; j += 8)
        t[ty + j][tx] = src[(size_t)(kb + ty + j) * N + nb + tx];
    __syncthreads();
#pragma unroll
    for (int j = 0; j < 32; j += 8)
        dst[(size_t)(nb + ty + j) * 1024 + kb + tx] = __float2half(t[tx][ty + j]);
}

// ---------------------------------------------------------------------------
// HMMA GEMM core: C[128,128] tile of A[M,1024] @ Bt[N,1024]^T (+bias)
// 2-stage cp.async double buffer (73.7KB smem -> 2 CTAs/SM), 1 sync/iter.
// ---------------------------------------------------------------------------
#define TILE_H (128 * 72)                      // halves per tile
#define GSMEM_BYTES (2 * 2 * TILE_H * 2)       // 2 stages x (A+B) = 73728 B

__device__ __forceinline__ void gemm_body(
    __half* sm, const __half* Ab, const __half* Bb,
    const float* __restrict__ bias, float* __restrict__ outF,
    int mode, int bx, int by)
{
    const int tid = threadIdx.x;
    const int lane = tid & 31, warp = tid >> 5;
    const int g = lane >> 2, tig = lane & 3;
    const int wm = warp & 3, wn = warp >> 2;
    const uint32_t smb = smem_u32(sm);

    int rowi[4], coli[4];
    uint32_t off16[4];
#pragma unroll
    for (int i = 0; i < 4; i++) {
        int s = tid + 256 * i;
        rowi[i] = s >> 3;
        coli[i] = (s & 7) * 8;
        off16[i] = rowi[i] * 144 + (s & 7) * 16;
    }
    const uint32_t aoff = ldsm_a_off(lane);
    const uint32_t boff = ldsm_b_off(lane);

    float acc[2][8][4];
#pragma unroll
    for (int mt = 0; mt < 2; mt++)
#pragma unroll
        for (int nt = 0; nt < 8; nt++)
#pragma unroll
            for (int q = 0; q < 4; q++) acc[mt][nt][q] = 0.f;

    // prologue: issue tile 0 into buf 0
    {
        const uint32_t sA = smb, sB = smb + TILE_H * 2;
#pragma unroll
        for (int i = 0; i < 4; i++) {
            CP_ASYNC16(sA + off16[i], Ab + (size_t)rowi[i] * 1024 + coli[i]);
            CP_ASYNC16(sB + off16[i], Bb + (size_t)rowi[i] * 1024 + coli[i]);
        }
        CP_COMMIT();
    }

    for (int kt = 0; kt < 16; kt++) {
        const int buf = kt & 1;
        CP_WAIT0();        // tile kt resident
        __syncthreads();   // all warps past reads of tile kt-1 (in buf^1)
        if (kt + 1 < 16) {
            const uint32_t sA = smb + (buf ^ 1) * 2 * TILE_H * 2;
            const uint32_t sB = sA + TILE_H * 2;
            const int k0 = (kt + 1) * 64;
#pragma unroll
            for (int i = 0; i < 4; i++) {
                CP_ASYNC16(sA + off16[i], Ab + (size_t)rowi[i] * 1024 + k0 + coli[i]);
                CP_ASYNC16(sB + off16[i], Bb + (size_t)rowi[i] * 1024 + k0 + coli[i]);
            }
            CP_COMMIT();
        }
        const uint32_t sA = smb + buf * 2 * TILE_H * 2;
        const uint32_t sB = sA + TILE_H * 2;
#pragma unroll
        for (int kk = 0; kk < 64; kk += 16) {
            uint32_t af[2][4];
#pragma unroll
            for (int mt = 0; mt < 2; mt++)
                LDSM_X4(af[mt][0], af[mt][1], af[mt][2], af[mt][3],
                        sA + (wm * 32 + mt * 16) * 144 + kk * 2 + aoff);
#pragma unroll
            for (int ntp = 0; ntp < 4; ntp++) {
                uint32_t b0a, b1a, b0b, b1b;
                LDSM_X4(b0a, b1a, b0b, b1b,
                        sB + (wn * 64 + ntp * 16) * 144 + kk * 2 + boff);
                mma16816(acc[0][2 * ntp],     af[0][0], af[0][1], af[0][2], af[0][3], b0a, b1a);
                mma16816(acc[0][2 * ntp + 1], af[0][0], af[0][1], af[0][2], af[0][3], b0b, b1b);
                mma16816(acc[1][2 * ntp],     af[1][0], af[1][1], af[1][2], af[1][3], b0a, b1a);
                mma16816(acc[1][2 * ntp + 1], af[1][0], af[1][1], af[1][2], af[1][3], b0b, b1b);
            }
        }
    }

    // epilogue (proven layout)
#pragma unroll
    for (int mt = 0; mt < 2; mt++) {
#pragma unroll
        for (int nt = 0; nt < 8; nt++) {
            int col = bx * 128 + wn * 64 + nt * 8 + 2 * tig;
            float bi0 = bias[col], bi1 = bias[col + 1];
#pragma unroll
            for (int hi = 0; hi < 2; hi++) {
                int row = by * 128 + wm * 32 + mt * 16 + g + hi * 8;
                float v0 = acc[mt][nt][hi * 2 + 0] + bi0;
                float v1 = acc[mt][nt][hi * 2 + 1] + bi1;
                if (mode == 2) {
                    *(float2*)(outF + (size_t)row * 1024 + col) = make_float2(v0, v1);
                } else if (mode == 1) {
                    int b = row >> 10, s = row & 1023;
                    int h = col >> 6, d = col & 63;
                    size_t idx = ((((size_t)b * HH + h) * SS + s) << 6) + d;
                    *(__half2*)(g_V + idx) = __floats2half2_rn(v0, v1);
                } else {
                    int b = row >> 10, s = row & 1023;
                    int h = col >> 7, w = col & 127;
                    int d = w & 63;
                    size_t idx = ((((size_t)b * HH + h) * SS + s) << 6) + d;
                    if (w < 64) *(__half2*)(g_Q + idx) = __floats2half2_rn(v0, v1);
                    else        *(__half2*)(g_K + idx) = __floats2half2_rn(v0, v1);
                }
            }
        }
    }
}

// Merged QK + V projection: grid (24, 64). bx<16 -> QK tile, else V tile.
__global__ __launch_bounds__(256, 2)
void gemm_proj(const float* __restrict__ bqk, const float* __restrict__ bv) {
    extern __shared__ __half sm[];
    const int by = blockIdx.y;
    if (blockIdx.x < 16) {
        gemm_body(sm, g_enc + (size_t)by * 128 * 1024,
                  g_WqkT + (size_t)blockIdx.x * 128 * 1024, bqk, nullptr, 0, blockIdx.x, by);
    } else {
        const int bx = blockIdx.x - 16;
        gemm_body(sm, g_query + (size_t)by * 128 * 1024,
                  g_WvT + (size_t)bx * 128 * 1024, bv, nullptr, 1, bx, by);
    }
}

// Output projection: grid (8, 64)
__global__ __launch_bounds__(256, 2)
void gemm_out(const float* __restrict__ bo, float* __restrict__ outF) {
    extern __shared__ __half sm[];
    gemm_body(sm, g_ctx + (size_t)blockIdx.y * 128 * 1024,
              g_WoT + (size_t)blockIdx.x * 128 * 1024, bo, outF, 2, blockIdx.x, blockIdx.y);
}

// ---------------------------------------------------------------------------
// Flash attention: grid (S/128, B*H), 256 threads (8 warps x 16 q-rows).
// cp.async double-buffered K/V, ldmatrix frags (V via .trans), online softmax.
// ---------------------------------------------------------------------------
#define T64 (64 * 72)
#define FSMEM_BYTES ((128 * 72 + 4 * T64) * 2)

__global__ __launch_bounds__(256, 2)
void flash_kernel() {
    extern __shared__ __half fsm[];
    __half* Qs = fsm;                    // [128][72]
    const uint32_t smb = smem_u32(fsm);
    const uint32_t qb = smb;
    const uint32_t kb0 = smb + 128 * 72 * 2;
    const uint32_t vb0 = kb0 + 2 * T64 * 2;

    const int tid = threadIdx.x;
    const int lane = tid & 31, warp = tid >> 5;
    const int g = lane >> 2, tig = lane & 3;
    const int bh = blockIdx.y;
    const int q0 = blockIdx.x * 128;
    const size_t base = (size_t)bh * SS * HD;

    const uint32_t aoff = ldsm_a_off(lane);
    const uint32_t boff = ldsm_b_off(lane);

    int krow[2], kcol[2];
    uint32_t koff[2];
#pragma unroll
    for (int i = 0; i < 2; i++) {
        int s = tid + 256 * i;
        krow[i] = s >> 3;
        kcol[i] = (s & 7) * 8;
        koff[i] = krow[i] * 144 + (s & 7) * 16;
    }

    // stage Q (scaled by 1/8, exact in fp16)
    const __half2 sc2 = __floats2half2_rn(0.125f, 0.125f);
#pragma unroll
    for (int i = 0; i < 4; i++) {
        int s = tid + 256 * i;
        int r = s >> 3, cg = s & 7;
        uint4 v = *(const uint4*)(g_Q + base + (size_t)(q0 + r) * HD + cg * 8);
        __half2* hv = (__half2*)&v;
        hv[0] = __hmul2(hv[0], sc2);
        hv[1] = __hmul2(hv[1], sc2);
        hv[2] = __hmul2(hv[2], sc2);
        hv[3] = __hmul2(hv[3], sc2);
        *(uint4*)&Qs[r * 72 + cg * 8] = v;
    }

    // issue tile 0
#pragma unroll
    for (int i = 0; i < 2; i++) {
        CP_ASYNC16(kb0 + koff[i], g_K + base + (size_t)krow[i] * HD + kcol[i]);
        CP_ASYNC16(vb0 + koff[i], g_V + base + (size_t)krow[i] * HD + kcol[i]);
    }
    CP_COMMIT();

    float o[8][4];
#pragma unroll
    for (int j = 0; j < 8; j++)
#pragma unroll
        for (int q = 0; q < 4; q++) o[j][q] = 0.f;
    float m0 = -1e30f, m1 = -1e30f, l0 = 0.f, l1 = 0.f;
    const float L2E = 1.44269504f;

    for (int it = 0; it < 16; it++) {
        const int buf = it & 1;
        __syncthreads();
        if (it + 1 < 16) {
            const int nb = buf ^ 1;
            const size_t src = base + (size_t)(it + 1) * 64 * HD;
#pragma unroll
            for (int i = 0; i < 2; i++) {
                CP_ASYNC16(kb0 + nb * T64 * 2 + koff[i], g_K + src + (size_t)krow[i] * HD + kcol[i]);
                CP_ASYNC16(vb0 + nb * T64 * 2 + koff[i], g_V + src + (size_t)krow[i] * HD + kcol[i]);
            }
            CP_COMMIT();
            CP_WAIT1();
        } else {
            CP_WAIT0();
        }
        __syncthreads();

        const uint32_t Kb = kb0 + buf * T64 * 2;
        const uint32_t Vb = vb0 + buf * T64 * 2;

        float sf[8][4];
#pragma unroll
        for (int nt = 0; nt < 8; nt++)
#pragma unroll
            for (int q = 0; q < 4; q++) sf[nt][q] = 0.f;
#pragma unroll
        for (int kk = 0; kk < 64; kk += 16) {
            uint32_t a0, a1, a2, a3;
            LDSM_X4(a0, a1, a2, a3, qb + (warp * 16) * 144 + kk * 2 + aoff);
#pragma unroll
            for (int ntp = 0; ntp < 4; ntp++) {
                uint32_t b0a, b1a, b0b, b1b;
                LDSM_X4(b0a, b1a, b0b, b1b, Kb + (ntp * 16) * 144 + kk * 2 + boff);
                mma16816(sf[2 * ntp],     a0, a1, a2, a3, b0a, b1a);
                mma16816(sf[2 * ntp + 1], a0, a1, a2, a3, b0b, b1b);
            }
        }

        float mx0 = -1e30f, mx1 = -1e30f;
#pragma unroll
        for (int nt = 0; nt < 8; nt++) {
            mx0 = fmaxf(mx0, fmaxf(sf[nt][0], sf[nt][1]));
            mx1 = fmaxf(mx1, fmaxf(sf[nt][2], sf[nt][3]));
        }
        mx0 = fmaxf(mx0, __shfl_xor_sync(0xffffffffu, mx0, 1));
        mx0 = fmaxf(mx0, __shfl_xor_sync(0xffffffffu, mx0, 2));
        mx1 = fmaxf(mx1, __shfl_xor_sync(0xffffffffu, mx1, 1));
        mx1 = fmaxf(mx1, __shfl_xor_sync(0xffffffffu, mx1, 2));
        float mn0 = fmaxf(m0, mx0), mn1 = fmaxf(m1, mx1);
        float al0 = exp2f((m0 - mn0) * L2E);
        float al1 = exp2f((m1 - mn1) * L2E);
        float rs0 = 0.f, rs1 = 0.f;
#pragma unroll
        for (int nt = 0; nt < 8; nt++) {
            sf[nt][0] = exp2f((sf[nt][0] - mn0) * L2E);
            sf[nt][1] = exp2f((sf[nt][1] - mn0) * L2E);
            sf[nt][2] = exp2f((sf[nt][2] - mn1) * L2E);
            sf[nt][3] = exp2f((sf[nt][3] - mn1) * L2E);
            rs0 += sf[nt][0] + sf[nt][1];
            rs1 += sf[nt][2] + sf[nt][3];
        }
        rs0 += __shfl_xor_sync(0xffffffffu, rs0, 1);
        rs0 += __shfl_xor_sync(0xffffffffu, rs0, 2);
        rs1 += __shfl_xor_sync(0xffffffffu, rs1, 1);
        rs1 += __shfl_xor_sync(0xffffffffu, rs1, 2);
        l0 = l0 * al0 + rs0;
        l1 = l1 * al1 + rs1;
        m0 = mn0;
        m1 = mn1;
#pragma unroll
        for (int j = 0; j < 8; j++) {
            o[j][0] *= al0; o[j][1] *= al0;
            o[j][2] *= al1; o[j][3] *= al1;
        }

#pragma unroll
        for (int kt = 0; kt < 4; kt++) {
            uint32_t a0 = pack_h2(sf[2 * kt][0], sf[2 * kt][1]);
            uint32_t a1 = pack_h2(sf[2 * kt][2], sf[2 * kt][3]);
            uint32_t a2 = pack_h2(sf[2 * kt + 1][0], sf[2 * kt + 1][1]);
            uint32_t a3 = pack_h2(sf[2 * kt + 1][2], sf[2 * kt + 1][3]);
#pragma unroll
            for (int jp = 0; jp < 4; jp++) {
                uint32_t v0, v1, v2, v3;
                LDSM_X4_T(v0, v1, v2, v3, Vb + (kt * 16) * 144 + (jp * 16) * 2 + aoff);
                mma16816(o[2 * jp],     a0, a1, a2, a3, v0, v1);
                mma16816(o[2 * jp + 1], a0, a1, a2, a3, v2, v3);
            }
        }
    }

    float il0 = 1.f / l0, il1 = 1.f / l1;
    int b = bh >> 4, h = bh & 15;
    int r0 = q0 + warp * 16 + g;
    size_t o0 = ((size_t)(b * SS + r0)) * DD + h * HD + 2 * tig;
    size_t o1 = o0 + (size_t)8 * DD;
#pragma unroll
    for (int j = 0; j < 8; j++) {
        *(__half2*)(g_ctx + o0 + j * 8) = __floats2half2_rn(o[j][0] * il0, o[j][1] * il0);
        *(__half2*)(g_ctx + o1 + j * 8) = __floats2half2_rn(o[j][2] * il1, o[j][3] * il1);
    }
}

// ---------------------------------------------------------------------------
// Launch (graph-capturable; default-stream ordering carries dependencies).
// Input order: input_query, encoding_output, Wqk, bqk, Wv, bv, Wo, bo
// ---------------------------------------------------------------------------
extern "C" void kernel_launch(void* const* d_in, const int* in_sizes, int n_in,
                              void* d_out, int out_size) {
    (void)in_sizes; (void)n_in; (void)out_size;
    const float* input_query = (const float*)d_in[0];
    const float* encoding    = (const float*)d_in[1];
    const float* Wqk         = (const float*)d_in[2];
    const float* bqk         = (const float*)d_in[3];
    const float* Wv          = (const float*)d_in[4];
    const float* bv          = (const float*)d_in[5];
    const float* Wo          = (const float*)d_in[6];
    const float* bo          = (const float*)d_in[7];
    float* out = (float*)d_out;

    cudaFuncSetAttribute(gemm_proj, cudaFuncAttributeMaxDynamicSharedMemorySize, GSMEM_BYTES);
    cudaFuncSetAttribute(gemm_out, cudaFuncAttributeMaxDynamicSharedMemorySize, GSMEM_BYTES);
    cudaFuncSetAttribute(flash_kernel, cudaFuncAttributeMaxDynamicSharedMemorySize, FSMEM_BYTES);

    convert_kernel<<<dim3(512, 1, 2), 256>>>(encoding, input_query);
    transpose_w<<<dim3(64, 32, 3), dim3(32, 8)>>>(Wqk, Wv, Wo);

    gemm_proj<<<dim3(24, 64), 256, GSMEM_BYTES>>>(bqk, bv);   // QK + V projections
    flash_kernel<<<dim3(8, 128), 256, FSMEM_BYTES>>>();        // attention
    gemm_out<<<dim3(8, 64), 256, GSMEM_BYTES>>>(bo, out);      // output projection
}

// round 13
// speedup vs baseline: 2.8052x; 1.0331x over previous
#include <cuda_runtime.h>
#include <cuda_fp16.h>
#include <cstdint>

// Problem dims (fixed by the dataset)
#define BB 8
#define SS 1024
#define DD 1024
#define HH 16
#define HD 64
#define MTOT (BB * SS)  // 8192

// ---------------------------------------------------------------------------
// Scratch (allocation-free rule: __device__ globals)
// ---------------------------------------------------------------------------
__device__ __align__(16) __half g_enc[MTOT * DD];
__device__ __align__(16) __half g_query[MTOT * DD];
__device__ __align__(16) __half g_WqkT[2 * DD * DD];    // Wqk^T [2048][1024] K-major
__device__ __align__(16) __half g_WvT[DD * DD];
__device__ __align__(16) __half g_WoT[DD * DD];
__device__ __align__(16) __half g_Q[MTOT * DD];         // [B,H,S,hd]
__device__ __align__(16) __half g_K[MTOT * DD];         // [B,H,S,hd]
__device__ __align__(16) __half g_V[MTOT * DD];         // [B,H,S,hd]
__device__ __align__(16) __half g_ctx[MTOT * DD];       // [B*S, H*hd]

// ---------------------------------------------------------------------------
// PTX helpers (baseline PTX — safe under compute_103 virtual arch)
// ---------------------------------------------------------------------------
__device__ __forceinline__ uint32_t smem_u32(const void* p) {
    uint32_t a;
    asm("{ .reg .u64 t; cvta.to.shared.u64 t, %1; cvt.u32.u64 %0, t; }" : "=r"(a) : "l"(p));
    return a;
}
#define CP_ASYNC16(dst, src) \
    asm volatile("cp.async.cg.shared.global [%0], [%1], 16;" :: "r"(dst), "l"(src))
#define CP_COMMIT() asm volatile("cp.async.commit_group;")
#define CP_WAIT0() asm volatile("cp.async.wait_group 0;" ::: "memory")
#define CP_WAIT1() asm volatile("cp.async.wait_group 1;" ::: "memory")

#define LDSM_X4(r0, r1, r2, r3, addr)                                         \
    asm volatile("ldmatrix.sync.aligned.m8n8.x4.shared.b16 {%0,%1,%2,%3}, [%4];" \
                 : "=r"(r0), "=r"(r1), "=r"(r2), "=r"(r3) : "r"(addr))
#define LDSM_X4_T(r0, r1, r2, r3, addr)                                       \
    asm volatile("ldmatrix.sync.aligned.m8n8.x4.trans.shared.b16 {%0,%1,%2,%3}, [%4];" \
                 : "=r"(r0), "=r"(r1), "=r"(r2), "=r"(r3) : "r"(addr))

__device__ __forceinline__ void mma16816(float* c,
                                         uint32_t a0, uint32_t a1, uint32_t a2, uint32_t a3,
                                         uint32_t b0, uint32_t b1) {
    asm volatile(
        "mma.sync.aligned.m16n8k16.row.col.f32.f16.f16.f32 "
        "{%0,%1,%2,%3}, {%4,%5,%6,%7}, {%8,%9}, {%0,%1,%2,%3};\n"
        : "+f"(c[0]), "+f"(c[1]), "+f"(c[2]), "+f"(c[3])
        : "r"(a0), "r"(a1), "r"(a2), "r"(a3), "r"(b0), "r"(b1));
}

__device__ __forceinline__ uint32_t pack_h2(float a, float b) {
    __half2 h = __floats2half2_rn(a, b);
    return *(uint32_t*)&h;
}

// Single-MUFU base-2 exponential (forces the fast path regardless of nvcc flags)
__device__ __forceinline__ float ex2(float x) {
    float y;
    asm("ex2.approx.ftz.f32 %0, %1;" : "=f"(y) : "f"(x));
    return y;
}

// Lane-dependent ldmatrix address offsets (bytes), 144B row pitch.
__device__ __forceinline__ uint32_t ldsm_a_off(int l) {
    return (uint32_t)(((l & 7) + (l & 8)) * 144 + ((l & 16) >> 1) * 2);
}
__device__ __forceinline__ uint32_t ldsm_b_off(int l) {
    return (uint32_t)(((l & 7) + ((l & 16) >> 1)) * 144 + (l & 8) * 2);
}

// ---------------------------------------------------------------------------
// Activations fp32 -> fp16 (blockIdx.z: 0=enc, 1=query)
// ---------------------------------------------------------------------------
__global__ void convert_kernel(const float* __restrict__ enc, const float* __restrict__ qry) {
    const float* src = blockIdx.z == 0 ? enc : qry;
    __half* dst = blockIdx.z == 0 ? g_enc : g_query;
    int i = blockIdx.x * blockDim.x + threadIdx.x;
    int stride = gridDim.x * blockDim.x;
    __half2* d2 = (__half2*)dst;
    const int n4 = MTOT * DD / 4;
    for (; i < n4; i += stride) {
        float4 v = ((const float4*)src)[i];
        d2[2 * i]     = __floats2half2_rn(v.x, v.y);
        d2[2 * i + 1] = __floats2half2_rn(v.z, v.w);
    }
}

// ---------------------------------------------------------------------------
// Weight transpose + convert, all three in one launch (blockIdx.z selects).
// ---------------------------------------------------------------------------
__global__ void transpose_w(const float* __restrict__ Wqk, const float* __restrict__ Wv,
                            const float* __restrict__ Wo) {
    __shared__ float t[32][33];
    const int z = blockIdx.z;
    if (z > 0 && blockIdx.x >= 32) return;
    const float* src = (z == 0) ? Wqk : (z == 1) ? Wv : Wo;
    __half* dst = (z == 0) ? g_WqkT : (z == 1) ? g_WvT : g_WoT;
    const int N = (z == 0) ? 2048 : 1024;
    const int nb = blockIdx.x * 32, kb = blockIdx.y * 32;
    const int tx = threadIdx.x, ty = threadIdx.y;  // 32 x 8
#pragma unroll
    for (int j = 0; j < 32; j += 8)
        t[ty + j][tx] = src[(size_t)(kb + ty + j) * N + nb + tx];
    __syncthreads();
#pragma unroll
    for (int j = 0; j < 32; j += 8)
        dst[(size_t)(nb + ty + j) * 1024 + kb + tx] = __float2half(t[tx][ty + j]);
}

// ---------------------------------------------------------------------------
// HMMA GEMM core: 128x128 tile, BK=64, 2-stage cp.async, 1 sync/iter.
// ---------------------------------------------------------------------------
#define TILE_H (128 * 72)
#define GSMEM_BYTES (2 * 2 * TILE_H * 2)

__device__ __forceinline__ void gemm_body(
    __half* sm, const __half* Ab, const __half* Bb,
    const float* __restrict__ bias, float* __restrict__ outF,
    int mode, int bx, int by)
{
    const int tid = threadIdx.x;
    const int lane = tid & 31, warp = tid >> 5;
    const int g = lane >> 2, tig = lane & 3;
    const int wm = warp & 3, wn = warp >> 2;
    const uint32_t smb = smem_u32(sm);

    int rowi[4], coli[4];
    uint32_t off16[4];
#pragma unroll
    for (int i = 0; i < 4; i++) {
        int s = tid + 256 * i;
        rowi[i] = s >> 3;
        coli[i] = (s & 7) * 8;
        off16[i] = rowi[i] * 144 + (s & 7) * 16;
    }
    const uint32_t aoff = ldsm_a_off(lane);
    const uint32_t boff = ldsm_b_off(lane);

    float acc[2][8][4];
#pragma unroll
    for (int mt = 0; mt < 2; mt++)
#pragma unroll
        for (int nt = 0; nt < 8; nt++)
#pragma unroll
            for (int q = 0; q < 4; q++) acc[mt][nt][q] = 0.f;

    {
        const uint32_t sA = smb, sB = smb + TILE_H * 2;
#pragma unroll
        for (int i = 0; i < 4; i++) {
            CP_ASYNC16(sA + off16[i], Ab + (size_t)rowi[i] * 1024 + coli[i]);
            CP_ASYNC16(sB + off16[i], Bb + (size_t)rowi[i] * 1024 + coli[i]);
        }
        CP_COMMIT();
    }

    for (int kt = 0; kt < 16; kt++) {
        const int buf = kt & 1;
        CP_WAIT0();
        __syncthreads();
        if (kt + 1 < 16) {
            const uint32_t sA = smb + (buf ^ 1) * 2 * TILE_H * 2;
            const uint32_t sB = sA + TILE_H * 2;
            const int k0 = (kt + 1) * 64;
#pragma unroll
            for (int i = 0; i < 4; i++) {
                CP_ASYNC16(sA + off16[i], Ab + (size_t)rowi[i] * 1024 + k0 + coli[i]);
                CP_ASYNC16(sB + off16[i], Bb + (size_t)rowi[i] * 1024 + k0 + coli[i]);
            }
            CP_COMMIT();
        }
        const uint32_t sA = smb + buf * 2 * TILE_H * 2;
        const uint32_t sB = sA + TILE_H * 2;
#pragma unroll
        for (int kk = 0; kk < 64; kk += 16) {
            uint32_t af[2][4];
#pragma unroll
            for (int mt = 0; mt < 2; mt++)
                LDSM_X4(af[mt][0], af[mt][1], af[mt][2], af[mt][3],
                        sA + (wm * 32 + mt * 16) * 144 + kk * 2 + aoff);
#pragma unroll
            for (int ntp = 0; ntp < 4; ntp++) {
                uint32_t b0a, b1a, b0b, b1b;
                LDSM_X4(b0a, b1a, b0b, b1b,
                        sB + (wn * 64 + ntp * 16) * 144 + kk * 2 + boff);
                mma16816(acc[0][2 * ntp],     af[0][0], af[0][1], af[0][2], af[0][3], b0a, b1a);
                mma16816(acc[0][2 * ntp + 1], af[0][0], af[0][1], af[0][2], af[0][3], b0b, b1b);
                mma16816(acc[1][2 * ntp],     af[1][0], af[1][1], af[1][2], af[1][3], b0a, b1a);
                mma16816(acc[1][2 * ntp + 1], af[1][0], af[1][1], af[1][2], af[1][3], b0b, b1b);
            }
        }
    }

#pragma unroll
    for (int mt = 0; mt < 2; mt++) {
#pragma unroll
        for (int nt = 0; nt < 8; nt++) {
            int col = bx * 128 + wn * 64 + nt * 8 + 2 * tig;
            float bi0 = bias[col], bi1 = bias[col + 1];
#pragma unroll
            for (int hi = 0; hi < 2; hi++) {
                int row = by * 128 + wm * 32 + mt * 16 + g + hi * 8;
                float v0 = acc[mt][nt][hi * 2 + 0] + bi0;
                float v1 = acc[mt][nt][hi * 2 + 1] + bi1;
                if (mode == 2) {
                    *(float2*)(outF + (size_t)row * 1024 + col) = make_float2(v0, v1);
                } else if (mode == 1) {
                    int b = row >> 10, s = row & 1023;
                    int h = col >> 6, d = col & 63;
                    size_t idx = ((((size_t)b * HH + h) * SS + s) << 6) + d;
                    *(__half2*)(g_V + idx) = __floats2half2_rn(v0, v1);
                } else {
                    int b = row >> 10, s = row & 1023;
                    int h = col >> 7, w = col & 127;
                    int d = w & 63;
                    size_t idx = ((((size_t)b * HH + h) * SS + s) << 6) + d;
                    if (w < 64) *(__half2*)(g_Q + idx) = __floats2half2_rn(v0, v1);
                    else        *(__half2*)(g_K + idx) = __floats2half2_rn(v0, v1);
                }
            }
        }
    }
}

__global__ __launch_bounds__(256, 2)
void gemm_proj(const float* __restrict__ bqk, const float* __restrict__ bv) {
    extern __shared__ __half sm[];
    const int by = blockIdx.y;
    if (blockIdx.x < 16) {
        gemm_body(sm, g_enc + (size_t)by * 128 * 1024,
                  g_WqkT + (size_t)blockIdx.x * 128 * 1024, bqk, nullptr, 0, blockIdx.x, by);
    } else {
        const int bx = blockIdx.x - 16;
        gemm_body(sm, g_query + (size_t)by * 128 * 1024,
                  g_WvT + (size_t)bx * 128 * 1024, bv, nullptr, 1, bx, by);
    }
}

__global__ __launch_bounds__(256, 2)
void gemm_out(const float* __restrict__ bo, float* __restrict__ outF) {
    extern __shared__ __half sm[];
    gemm_body(sm, g_ctx + (size_t)blockIdx.y * 128 * 1024,
              g_WoT + (size_t)blockIdx.x * 128 * 1024, bo, outF, 2, blockIdx.x, blockIdx.y);
}

// ---------------------------------------------------------------------------
// Flash attention: grid (S/128, B*H), 256 threads (8 warps x 16 q-rows).
// Q fragments hoisted to registers (loaded once); single-MUFU ex2 softmax;
// cp.async double-buffered K/V; ldmatrix frags (V via .trans).
// ---------------------------------------------------------------------------
#define T64 (64 * 72)
#define FSMEM_BYTES ((128 * 72 + 4 * T64) * 2)

__global__ __launch_bounds__(256, 2)
void flash_kernel() {
    extern __shared__ __half fsm[];
    __half* Qs = fsm;                    // [128][72] (read once, then dead)
    const uint32_t smb = smem_u32(fsm);
    const uint32_t qb = smb;
    const uint32_t kb0 = smb + 128 * 72 * 2;
    const uint32_t vb0 = kb0 + 2 * T64 * 2;

    const int tid = threadIdx.x;
    const int lane = tid & 31, warp = tid >> 5;
    const int g = lane >> 2, tig = lane & 3;
    const int bh = blockIdx.y;
    const int q0 = blockIdx.x * 128;
    const size_t base = (size_t)bh * SS * HD;

    const uint32_t aoff = ldsm_a_off(lane);
    const uint32_t boff = ldsm_b_off(lane);

    int krow[2], kcol[2];
    uint32_t koff[2];
#pragma unroll
    for (int i = 0; i < 2; i++) {
        int s = tid + 256 * i;
        krow[i] = s >> 3;
        kcol[i] = (s & 7) * 8;
        koff[i] = krow[i] * 144 + (s & 7) * 16;
    }

    // stage Q (scaled by 1/8, exact in fp16)
    const __half2 sc2 = __floats2half2_rn(0.125f, 0.125f);
#pragma unroll
    for (int i = 0; i < 4; i++) {
        int s = tid + 256 * i;
        int r = s >> 3, cg = s & 7;
        uint4 v = *(const uint4*)(g_Q + base + (size_t)(q0 + r) * HD + cg * 8);
        __half2* hv = (__half2*)&v;
        hv[0] = __hmul2(hv[0], sc2);
        hv[1] = __hmul2(hv[1], sc2);
        hv[2] = __hmul2(hv[2], sc2);
        hv[3] = __hmul2(hv[3], sc2);
        *(uint4*)&Qs[r * 72 + cg * 8] = v;
    }

    // issue K/V tile 0
#pragma unroll
    for (int i = 0; i < 2; i++) {
        CP_ASYNC16(kb0 + koff[i], g_K + base + (size_t)krow[i] * HD + kcol[i]);
        CP_ASYNC16(vb0 + koff[i], g_V + base + (size_t)krow[i] * HD + kcol[i]);
    }
    CP_COMMIT();

    // hoist Q fragments into registers (16 regs), smem Q then dead
    __syncthreads();
    uint32_t qf[4][4];
#pragma unroll
    for (int kk4 = 0; kk4 < 4; kk4++)
        LDSM_X4(qf[kk4][0], qf[kk4][1], qf[kk4][2], qf[kk4][3],
                qb + (warp * 16) * 144 + kk4 * 32 + aoff);

    float o[8][4];
#pragma unroll
    for (int j = 0; j < 8; j++)
#pragma unroll
        for (int q = 0; q < 4; q++) o[j][q] = 0.f;
    float m0 = -1e30f, m1 = -1e30f, l0 = 0.f, l1 = 0.f;
    const float L2E = 1.44269504f;

    for (int it = 0; it < 16; it++) {
        const int buf = it & 1;
        __syncthreads();   // readers of buf^1 (prefetch target) are done
        if (it + 1 < 16) {
            const int nb = buf ^ 1;
            const size_t src = base + (size_t)(it + 1) * 64 * HD;
#pragma unroll
            for (int i = 0; i < 2; i++) {
                CP_ASYNC16(kb0 + nb * T64 * 2 + koff[i], g_K + src + (size_t)krow[i] * HD + kcol[i]);
                CP_ASYNC16(vb0 + nb * T64 * 2 + koff[i], g_V + src + (size_t)krow[i] * HD + kcol[i]);
            }
            CP_COMMIT();
            CP_WAIT1();
        } else {
            CP_WAIT0();
        }
        __syncthreads();   // tile 'it' visible to all warps

        const uint32_t Kb = kb0 + buf * T64 * 2;
        const uint32_t Vb = vb0 + buf * T64 * 2;

        // S = Q @ K^T (Q fragments from registers)
        float sf[8][4];
#pragma unroll
        for (int nt = 0; nt < 8; nt++)
#pragma unroll
            for (int q = 0; q < 4; q++) sf[nt][q] = 0.f;
#pragma unroll
        for (int kk4 = 0; kk4 < 4; kk4++) {
#pragma unroll
            for (int ntp = 0; ntp < 4; ntp++) {
                uint32_t b0a, b1a, b0b, b1b;
                LDSM_X4(b0a, b1a, b0b, b1b, Kb + (ntp * 16) * 144 + kk4 * 32 + boff);
                mma16816(sf[2 * ntp],     qf[kk4][0], qf[kk4][1], qf[kk4][2], qf[kk4][3], b0a, b1a);
                mma16816(sf[2 * ntp + 1], qf[kk4][0], qf[kk4][1], qf[kk4][2], qf[kk4][3], b0b, b1b);
            }
        }

        // online softmax (single-MUFU exponentials)
        float mx0 = -1e30f, mx1 = -1e30f;
#pragma unroll
        for (int nt = 0; nt < 8; nt++) {
            mx0 = fmaxf(mx0, fmaxf(sf[nt][0], sf[nt][1]));
            mx1 = fmaxf(mx1, fmaxf(sf[nt][2], sf[nt][3]));
        }
        mx0 = fmaxf(mx0, __shfl_xor_sync(0xffffffffu, mx0, 1));
        mx0 = fmaxf(mx0, __shfl_xor_sync(0xffffffffu, mx0, 2));
        mx1 = fmaxf(mx1, __shfl_xor_sync(0xffffffffu, mx1, 1));
        mx1 = fmaxf(mx1, __shfl_xor_sync(0xffffffffu, mx1, 2));
        float mn0 = fmaxf(m0, mx0), mn1 = fmaxf(m1, mx1);
        float al0 = ex2((m0 - mn0) * L2E);
        float al1 = ex2((m1 - mn1) * L2E);
        float rs0 = 0.f, rs1 = 0.f;
#pragma unroll
        for (int nt = 0; nt < 8; nt++) {
            sf[nt][0] = ex2((sf[nt][0] - mn0) * L2E);
            sf[nt][1] = ex2((sf[nt][1] - mn0) * L2E);
            sf[nt][2] = ex2((sf[nt][2] - mn1) * L2E);
            sf[nt][3] = ex2((sf[nt][3] - mn1) * L2E);
            rs0 += sf[nt][0] + sf[nt][1];
            rs1 += sf[nt][2] + sf[nt][3];
        }
        rs0 += __shfl_xor_sync(0xffffffffu, rs0, 1);
        rs0 += __shfl_xor_sync(0xffffffffu, rs0, 2);
        rs1 += __shfl_xor_sync(0xffffffffu, rs1, 1);
        rs1 += __shfl_xor_sync(0xffffffffu, rs1, 2);
        l0 = l0 * al0 + rs0;
        l1 = l1 * al1 + rs1;
        m0 = mn0;
        m1 = mn1;
#pragma unroll
        for (int j = 0; j < 8; j++) {
            o[j][0] *= al0; o[j][1] *= al0;
            o[j][2] *= al1; o[j][3] *= al1;
        }

        // O += P @ V  (V via ldmatrix.trans)
#pragma unroll
        for (int kt = 0; kt < 4; kt++) {
            uint32_t a0 = pack_h2(sf[2 * kt][0], sf[2 * kt][1]);
            uint32_t a1 = pack_h2(sf[2 * kt][2], sf[2 * kt][3]);
            uint32_t a2 = pack_h2(sf[2 * kt + 1][0], sf[2 * kt + 1][1]);
            uint32_t a3 = pack_h2(sf[2 * kt + 1][2], sf[2 * kt + 1][3]);
#pragma unroll
            for (int jp = 0; jp < 4; jp++) {
                uint32_t v0, v1, v2, v3;
                LDSM_X4_T(v0, v1, v2, v3, Vb + (kt * 16) * 144 + (jp * 16) * 2 + aoff);
                mma16816(o[2 * jp],     a0, a1, a2, a3, v0, v1);
                mma16816(o[2 * jp + 1], a0, a1, a2, a3, v2, v3);
            }
        }
    }

    float il0 = 1.f / l0, il1 = 1.f / l1;
    int b = bh >> 4, h = bh & 15;
    int r0 = q0 + warp * 16 + g;
    size_t o0 = ((size_t)(b * SS + r0)) * DD + h * HD + 2 * tig;
    size_t o1 = o0 + (size_t)8 * DD;
#pragma unroll
    for (int j = 0; j < 8; j++) {
        *(__half2*)(g_ctx + o0 + j * 8) = __floats2half2_rn(o[j][0] * il0, o[j][1] * il0);
        *(__half2*)(g_ctx + o1 + j * 8) = __floats2half2_rn(o[j][2] * il1, o[j][3] * il1);
    }
}

// ---------------------------------------------------------------------------
// Launch (graph-capturable; default-stream ordering carries dependencies).
// Input order: input_query, encoding_output, Wqk, bqk, Wv, bv, Wo, bo
// ---------------------------------------------------------------------------
extern "C" void kernel_launch(void* const* d_in, const int* in_sizes, int n_in,
                              void* d_out, int out_size) {
    (void)in_sizes; (void)n_in; (void)out_size;
    const float* input_query = (const float*)d_in[0];
    const float* encoding    = (const float*)d_in[1];
    const float* Wqk         = (const float*)d_in[2];
    const float* bqk         = (const float*)d_in[3];
    const float* Wv          = (const float*)d_in[4];
    const float* bv          = (const float*)d_in[5];
    const float* Wo          = (const float*)d_in[6];
    const float* bo          = (const float*)d_in[7];
    float* out = (float*)d_out;

    cudaFuncSetAttribute(gemm_proj, cudaFuncAttributeMaxDynamicSharedMemorySize, GSMEM_BYTES);
    cudaFuncSetAttribute(gemm_out, cudaFuncAttributeMaxDynamicSharedMemorySize, GSMEM_BYTES);
    cudaFuncSetAttribute(flash_kernel, cudaFuncAttributeMaxDynamicSharedMemorySize, FSMEM_BYTES);

    convert_kernel<<<dim3(512, 1, 2), 256>>>(encoding, input_query);
    transpose_w<<<dim3(64, 32, 3), dim3(32, 8)>>>(Wqk, Wv, Wo);

    gemm_proj<<<dim3(24, 64), 256, GSMEM_BYTES>>>(bqk, bv);   // QK + V projections
    flash_kernel<<<dim3(8, 128), 256, FSMEM_BYTES>>>();        // attention
    gemm_out<<<dim3(8, 64), 256, GSMEM_BYTES>>>(bo, out);      // output projection
}